// round 14
// baseline (speedup 1.0000x reference)
#include <cuda_runtime.h>
#include <math.h>
#include <stdint.h>

#define BB 4
#define KQn 192
#define KPn 192
#define Hn 256
#define Tn 32
#define Rn 768
#define NEGV (-1e9f)
#define SCALEV (0.17677669529663687f)   // 1/sqrt(32)
#define SPAD 36

// ---------------- scratch ----------------
static __device__ float g_A1[BB * KQn * Tn];
static __device__ float g_A2[BB * KPn * Tn];
static __device__ float g_u1[BB * KQn];
static __device__ float g_u2[BB * KPn];
static __device__ float g_fq[BB * KPn * KQn * Tn];  // tf32-rounded
static __device__ float g_fk[BB * KPn * KQn * Tn];  // tf32-rounded, pre-scaled by obv*SCALE
static __device__ float g_vw[BB * KPn * KQn];
static __device__ float g_wv4[Tn];
static __device__ float g_c0[1];
static __device__ float g_Umh[BB * KPn * KQn];
static __device__ float g_Umv[BB * KPn * KQn];
static __device__ float g_U[BB * KPn * KQn];
static __device__ float g_Gl[BB * KPn * Rn];
static __device__ float g_Gr[BB * KQn * Rn];
static __device__ float g_left[BB * KPn * Rn];
static __device__ float g_right[BB * KQn * Rn];
static __device__ float g_part[4 * BB * KPn * KQn];

__device__ __forceinline__ uint32_t tf32cvt(float x) {
    uint32_t u;
    asm("cvt.rna.tf32.f32 %0, %1;" : "=r"(u) : "f"(x));
    return u;
}

__device__ __forceinline__ void mma_tf32(float c[4], const uint32_t a[4], uint32_t b0, uint32_t b1) {
    asm volatile("mma.sync.aligned.m16n8k8.row.col.f32.tf32.tf32.f32 "
        "{%0,%1,%2,%3}, {%4,%5,%6,%7}, {%8,%9}, {%0,%1,%2,%3};"
        : "+f"(c[0]), "+f"(c[1]), "+f"(c[2]), "+f"(c[3])
        : "r"(a[0]), "r"(a[1]), "r"(a[2]), "r"(a[3]), "r"(b0), "r"(b1));
}

// ---------------- K0: per-row projections A1/A2 and u1/u2 ----------------
__global__ __launch_bounds__(256) void k0_rowproj(
    const float* __restrict__ Eq, const float* __restrict__ Ep,
    const float* __restrict__ W_in, const float* __restrict__ W_out)
{
    const int b = blockIdx.x;
    const int side = blockIdx.y;
    const float* src = side ? (Ep + b * KPn * Hn) : (Eq + b * KQn * Hn);
    const int woff = side ? Hn : 0;
    float* A = side ? (g_A2 + b * KPn * Tn) : (g_A1 + b * KQn * Tn);
    float* u = side ? (g_u2 + b * KPn) : (g_u1 + b * KQn);

    __shared__ float sW[Tn][Hn + 1];
    __shared__ float swv[Hn];
    const int tid = threadIdx.y * 32 + threadIdx.x;
    for (int i = tid; i < Tn * Hn; i += 256) {
        int t = i >> 8, h = i & 255;
        sW[t][h] = W_in[t * Rn + woff + h];
    }
    for (int i = tid; i < Hn; i += 256) swv[i] = W_out[woff + i];
    __syncthreads();

    const int t = threadIdx.x;
    const int y0 = blockIdx.z * 48;
    for (int y = y0 + threadIdx.y; y < y0 + 48; y += 8) {
        const float* row = src + y * Hn;
        float p0 = 0.f, p1 = 0.f, p2 = 0.f, p3 = 0.f, up = 0.f;
        for (int h = 0; h < Hn; h += 4) {
            p0 += row[h] * sW[t][h];
            p1 += row[h + 1] * sW[t][h + 1];
            p2 += row[h + 2] * sW[t][h + 2];
            p3 += row[h + 3] * sW[t][h + 3];
        }
        for (int h = t; h < Hn; h += 32) up += row[h] * swv[h];
        #pragma unroll
        for (int o = 16; o; o >>= 1) up += __shfl_down_sync(0xffffffffu, up, o);
        A[y * Tn + t] = (p0 + p1) + (p2 + p3);
        if (t == 0) u[y] = up;
    }
}

// ---------------- K0b: wv4 = Wv^T @ w4, c0 = bv . w4 ----------------
__global__ void k0b_wv4(const float* __restrict__ Wv, const float* __restrict__ bv,
                        const float* __restrict__ W_out)
{
    const int t = threadIdx.x;
    float s = 0.f;
    for (int u = 0; u < Tn; u++) s += Wv[u * Tn + t] * W_out[Rn + u];
    g_wv4[t] = s;
    float c = bv[t] * W_out[Rn + t];
    #pragma unroll
    for (int o = 16; o; o >>= 1) c += __shfl_down_sync(0xffffffffu, c, o);
    if (t == 0) g_c0[0] = c;
}

// ---------------- K1: bilinear MMA -> E1 -> projection MMA; warp-local barriers ----------------
__global__ __launch_bounds__(192) void k1_pair(
    const float* __restrict__ Eq, const float* __restrict__ Ep,
    const float* __restrict__ W_in,
    const float* __restrict__ Wq, const float* __restrict__ bq,
    const float* __restrict__ Wk, const float* __restrict__ bk,
    const float* __restrict__ Wo1, const float* __restrict__ bo1,
    const float* __restrict__ Wo2, const float* __restrict__ bo2)
{
    extern __shared__ uint32_t smem[];
    uint32_t* sW3 = smem;                                   // 32*260 (>= 104*36)
    uint32_t* sA = sW3 + 32 * 260;                          // 192*36
    float* sE1f = reinterpret_cast<float*>(sA);
    float* sEpRow = reinterpret_cast<float*>(sA + 192 * 36);
    float* sA2 = sEpRow + Hn;

    const int b = blockIdx.x, p = blockIdx.y;
    const int tid = threadIdx.x;
    const int wid = tid >> 5, lane = tid & 31, g = lane >> 2, t4 = lane & 3;
    const int m0 = wid * 32;

    for (int i = tid; i < 32 * 64; i += 192) {
        const int t = i >> 6, h4 = i & 63;
        float4 w = reinterpret_cast<const float4*>(W_in + t * Rn + 2 * Hn)[h4];
        uint32_t* d = sW3 + t * 260 + h4 * 4;
        d[0] = tf32cvt(w.x); d[1] = tf32cvt(w.y); d[2] = tf32cvt(w.z); d[3] = tf32cvt(w.w);
    }
    for (int i = tid; i < Hn / 4; i += 192)
        reinterpret_cast<float4*>(sEpRow)[i] =
            reinterpret_cast<const float4*>(Ep + (b * KPn + p) * Hn)[i];
    if (tid < Tn) sA2[tid] = g_A2[(b * KPn + p) * Tn + tid];
    __syncthreads();

    // ---- stage 1: bilinear E1 = (Eq o Ep) @ W3^T (warp-local A tiles) ----
    float c1[2][4][4] = {};
    const float4* eqrow = reinterpret_cast<const float4*>(Eq + (b * KQn + tid) * Hn);
    const float4* sEpRow4 = reinterpret_cast<const float4*>(sEpRow);

    for (int kc = 0; kc < 8; kc++) {
        #pragma unroll
        for (int j = 0; j < 8; j++) {
            float4 e = eqrow[kc * 8 + j];
            float4 pp = sEpRow4[kc * 8 + j];
            uint32_t* d = sA + tid * 36 + j * 4;
            d[0] = tf32cvt(e.x * pp.x); d[1] = tf32cvt(e.y * pp.y);
            d[2] = tf32cvt(e.z * pp.z); d[3] = tf32cvt(e.w * pp.w);
        }
        __syncwarp();
        #pragma unroll
        for (int ks = 0; ks < 4; ks++) {
            uint32_t a[2][4];
            #pragma unroll
            for (int mt = 0; mt < 2; mt++) {
                const int r = m0 + mt * 16;
                a[mt][0] = sA[(r + g) * 36 + ks * 8 + t4];
                a[mt][1] = sA[(r + g + 8) * 36 + ks * 8 + t4];
                a[mt][2] = sA[(r + g) * 36 + ks * 8 + t4 + 4];
                a[mt][3] = sA[(r + g + 8) * 36 + ks * 8 + t4 + 4];
            }
            #pragma unroll
            for (int nt = 0; nt < 4; nt++) {
                const uint32_t b0 = sW3[(nt * 8 + g) * 260 + kc * 32 + ks * 8 + t4];
                const uint32_t b1 = sW3[(nt * 8 + g) * 260 + kc * 32 + ks * 8 + t4 + 4];
                mma_tf32(c1[0][nt], a[0], b0, b1);
                mma_tf32(c1[1][nt], a[1], b0, b1);
            }
        }
        __syncwarp();
    }

    #pragma unroll
    for (int mt = 0; mt < 2; mt++)
        #pragma unroll
        for (int nt = 0; nt < 4; nt++) {
            const int r0 = m0 + mt * 16 + g;
            const int col = nt * 8 + 2 * t4;
            sE1f[r0 * 36 + col] = c1[mt][nt][0];
            sE1f[r0 * 36 + col + 1] = c1[mt][nt][1];
            sE1f[(r0 + 8) * 36 + col] = c1[mt][nt][2];
            sE1f[(r0 + 8) * 36 + col + 1] = c1[mt][nt][3];
        }
    __syncwarp();

    {
        const int q = tid;
        const float4* a1 = reinterpret_cast<const float4*>(g_A1 + (b * KQn + q) * Tn);
        #pragma unroll
        for (int i4 = 0; i4 < 8; i4++) {
            float4 ev = *reinterpret_cast<const float4*>(&sE1f[q * 36 + i4 * 4]);
            float4 a = a1[i4];
            uint32_t* d = sA + q * 36 + i4 * 4;
            d[0] = tf32cvt(ev.x + a.x + sA2[i4 * 4 + 0]);
            d[1] = tf32cvt(ev.y + a.y + sA2[i4 * 4 + 1]);
            d[2] = tf32cvt(ev.z + a.z + sA2[i4 * 4 + 2]);
            d[3] = tf32cvt(ev.w + a.w + sA2[i4 * 4 + 3]);
        }
    }
    __syncthreads();

    for (int i = tid; i < 96 * 32; i += 192) {
        const int n = i >> 5, t = i & 31;
        float w = (n < 32) ? Wo1[n * 32 + t] : (n < 64) ? Wq[(n - 32) * 32 + t] : Wk[(n - 64) * 32 + t];
        sW3[n * 36 + t] = tf32cvt(w);
    }
    if (tid < 32) sW3[96 * 36 + tid] = tf32cvt(g_wv4[tid]);
    for (int i = tid; i < 7 * 36; i += 192) sW3[97 * 36 + i] = 0u;
    __syncthreads();

    const int pairbase = (b * KPn + p) * KQn;
    const float bo2v = bo2[0];
    const float c0v = g_c0[0];
    float scReg[4];

    // G0: Wo1 -> sc
    {
        float c[2][4][4] = {};
        #pragma unroll
        for (int ks = 0; ks < 4; ks++) {
            uint32_t a[2][4];
            #pragma unroll
            for (int mt = 0; mt < 2; mt++) {
                const int r = m0 + mt * 16;
                a[mt][0] = sA[(r + g) * 36 + ks * 8 + t4];
                a[mt][1] = sA[(r + g + 8) * 36 + ks * 8 + t4];
                a[mt][2] = sA[(r + g) * 36 + ks * 8 + t4 + 4];
                a[mt][3] = sA[(r + g + 8) * 36 + ks * 8 + t4 + 4];
            }
            #pragma unroll
            for (int nt = 0; nt < 4; nt++) {
                const uint32_t b0 = sW3[(nt * 8 + g) * 36 + ks * 8 + t4];
                const uint32_t b1 = sW3[(nt * 8 + g) * 36 + ks * 8 + t4 + 4];
                mma_tf32(c[0][nt], a[0], b0, b1);
                mma_tf32(c[1][nt], a[1], b0, b1);
            }
        }
        #pragma unroll
        for (int mt = 0; mt < 2; mt++)
            #pragma unroll
            for (int half = 0; half < 2; half++) {
                float part = 0.f;
                #pragma unroll
                for (int nt = 0; nt < 4; nt++) {
                    const int col = nt * 8 + 2 * t4;
                    part += fmaxf(c[mt][nt][half * 2 + 0] + bo1[col], 0.f) * Wo2[col]
                          + fmaxf(c[mt][nt][half * 2 + 1] + bo1[col + 1], 0.f) * Wo2[col + 1];
                }
                part += __shfl_xor_sync(0xffffffffu, part, 1);
                part += __shfl_xor_sync(0xffffffffu, part, 2);
                scReg[mt * 2 + half] = SCALEV / (1.f + __expf(-(part + bo2v)));
            }
    }

    // G1: Wq -> g_fq
    {
        float c[2][4][4] = {};
        #pragma unroll
        for (int ks = 0; ks < 4; ks++) {
            uint32_t a[2][4];
            #pragma unroll
            for (int mt = 0; mt < 2; mt++) {
                const int r = m0 + mt * 16;
                a[mt][0] = sA[(r + g) * 36 + ks * 8 + t4];
                a[mt][1] = sA[(r + g + 8) * 36 + ks * 8 + t4];
                a[mt][2] = sA[(r + g) * 36 + ks * 8 + t4 + 4];
                a[mt][3] = sA[(r + g + 8) * 36 + ks * 8 + t4 + 4];
            }
            #pragma unroll
            for (int nt = 0; nt < 4; nt++) {
                const uint32_t b0 = sW3[(32 + nt * 8 + g) * 36 + ks * 8 + t4];
                const uint32_t b1 = sW3[(32 + nt * 8 + g) * 36 + ks * 8 + t4 + 4];
                mma_tf32(c[0][nt], a[0], b0, b1);
                mma_tf32(c[1][nt], a[1], b0, b1);
            }
        }
        #pragma unroll
        for (int mt = 0; mt < 2; mt++)
            #pragma unroll
            for (int nt = 0; nt < 4; nt++) {
                const int r0 = m0 + mt * 16 + g;
                const int col = nt * 8 + 2 * t4;
                const float b0f = bq[col], b1f = bq[col + 1];
                float2 v0 = make_float2(__uint_as_float(tf32cvt(c[mt][nt][0] + b0f)),
                                        __uint_as_float(tf32cvt(c[mt][nt][1] + b1f)));
                float2 v1 = make_float2(__uint_as_float(tf32cvt(c[mt][nt][2] + b0f)),
                                        __uint_as_float(tf32cvt(c[mt][nt][3] + b1f)));
                *reinterpret_cast<float2*>(g_fq + (pairbase + r0) * Tn + col) = v0;
                *reinterpret_cast<float2*>(g_fq + (pairbase + r0 + 8) * Tn + col) = v1;
            }
    }

    // G2: Wk + wv4 -> g_fk + g_vw
    {
        float c[2][5][4] = {};
        #pragma unroll
        for (int ks = 0; ks < 4; ks++) {
            uint32_t a[2][4];
            #pragma unroll
            for (int mt = 0; mt < 2; mt++) {
                const int r = m0 + mt * 16;
                a[mt][0] = sA[(r + g) * 36 + ks * 8 + t4];
                a[mt][1] = sA[(r + g + 8) * 36 + ks * 8 + t4];
                a[mt][2] = sA[(r + g) * 36 + ks * 8 + t4 + 4];
                a[mt][3] = sA[(r + g + 8) * 36 + ks * 8 + t4 + 4];
            }
            #pragma unroll
            for (int nt = 0; nt < 5; nt++) {
                const uint32_t b0 = sW3[(64 + nt * 8 + g) * 36 + ks * 8 + t4];
                const uint32_t b1 = sW3[(64 + nt * 8 + g) * 36 + ks * 8 + t4 + 4];
                mma_tf32(c[0][nt], a[0], b0, b1);
                mma_tf32(c[1][nt], a[1], b0, b1);
            }
        }
        #pragma unroll
        for (int mt = 0; mt < 2; mt++)
            #pragma unroll
            for (int nt = 0; nt < 4; nt++) {
                const int r0 = m0 + mt * 16 + g;
                const int col = nt * 8 + 2 * t4;
                const float b0f = bk[col], b1f = bk[col + 1];
                const float s0 = scReg[mt * 2 + 0], s1 = scReg[mt * 2 + 1];
                float2 v0 = make_float2(__uint_as_float(tf32cvt((c[mt][nt][0] + b0f) * s0)),
                                        __uint_as_float(tf32cvt((c[mt][nt][1] + b1f) * s0)));
                float2 v1 = make_float2(__uint_as_float(tf32cvt((c[mt][nt][2] + b0f) * s1)),
                                        __uint_as_float(tf32cvt((c[mt][nt][3] + b1f) * s1)));
                *reinterpret_cast<float2*>(g_fk + (pairbase + r0) * Tn + col) = v0;
                *reinterpret_cast<float2*>(g_fk + (pairbase + r0 + 8) * Tn + col) = v1;
            }
        if (t4 == 0) {
            #pragma unroll
            for (int mt = 0; mt < 2; mt++) {
                const int r0 = m0 + mt * 16 + g;
                g_vw[pairbase + r0] = c[mt][4][0] + c0v;
                g_vw[pairbase + r0 + 8] = c[mt][4][2] + c0v;
            }
        }
    }
}

// ================= tensor-core attention core (aF from registers) =================
__device__ __forceinline__ void attn_mma_core(
    const uint32_t aF[4][2][4], const uint32_t* __restrict__ sfk,
    const float2* __restrict__ sbv, int tid, float sOut[4], float tOut[4], int rows[4])
{
    const int wid = tid >> 5, lane = tid & 31;
    const int g = lane >> 2, t4 = lane & 3;
    const int m0 = wid * 32;

    float s[4] = {0.f, 0.f, 0.f, 0.f}, tt[4] = {0.f, 0.f, 0.f, 0.f};

    for (int nc = 0; nc < 192; nc += 32) {
        float c[2][4][4];
        #pragma unroll
        for (int mt = 0; mt < 2; mt++)
            #pragma unroll
            for (int nt = 0; nt < 4; nt++)
                #pragma unroll
                for (int r = 0; r < 4; r++) c[mt][nt][r] = 0.f;

        #pragma unroll
        for (int ks = 0; ks < 4; ks++)
            #pragma unroll
            for (int nt = 0; nt < 4; nt++) {
                const uint32_t b0 = sfk[(nc + nt * 8 + g) * SPAD + ks * 8 + t4];
                const uint32_t b1 = sfk[(nc + nt * 8 + g) * SPAD + ks * 8 + t4 + 4];
                mma_tf32(c[0][nt], aF[ks][0], b0, b1);
                mma_tf32(c[1][nt], aF[ks][1], b0, b1);
            }

        #pragma unroll
        for (int nt = 0; nt < 4; nt++) {
            const int col0 = nc + nt * 8 + 2 * t4;
            const float2 bv0 = sbv[col0];
            const float2 bv1 = sbv[col0 + 1];
            #pragma unroll
            for (int mt = 0; mt < 2; mt++) {
                const float e0 = __expf(c[mt][nt][0] + bv0.x);
                const float e1 = __expf(c[mt][nt][1] + bv1.x);
                const float e2 = __expf(c[mt][nt][2] + bv0.x);
                const float e3 = __expf(c[mt][nt][3] + bv1.x);
                s[mt * 2 + 0] += e0 + e1;
                tt[mt * 2 + 0] += e0 * bv0.y + e1 * bv1.y;
                s[mt * 2 + 1] += e2 + e3;
                tt[mt * 2 + 1] += e2 * bv0.y + e3 * bv1.y;
            }
        }
    }

    #pragma unroll
    for (int i = 0; i < 4; i++) {
        s[i] += __shfl_xor_sync(0xffffffffu, s[i], 1);
        s[i] += __shfl_xor_sync(0xffffffffu, s[i], 2);
        tt[i] += __shfl_xor_sync(0xffffffffu, tt[i], 1);
        tt[i] += __shfl_xor_sync(0xffffffffu, tt[i], 2);
        sOut[i] = s[i]; tOut[i] = tt[i];
    }
    rows[0] = m0 + g;
    rows[1] = m0 + g + 8;
    rows[2] = m0 + 16 + g;
    rows[3] = m0 + 24 + g;
}

// ---------------- K23: both attention directions (z = dir); fq frags from global ----------------
__global__ __launch_bounds__(192) void k23_attn(const float* __restrict__ mask)
{
    extern __shared__ uint32_t smem[];
    uint32_t* sfk = smem;                                    // 192*SPAD
    float2* sbv = reinterpret_cast<float2*>(sfk + 192 * SPAD);

    const int b = blockIdx.x, y = blockIdx.y, dir = blockIdx.z;
    const int tid = threadIdx.x;
    const int wid = tid >> 5, lane = tid & 31, g = lane >> 2, t4 = lane & 3;
    const int m0 = wid * 32;

    const uint32_t* fqg = reinterpret_cast<const uint32_t*>(g_fq);
    uint32_t aF[4][2][4];

    if (dir == 0) {
        const int base = (b * KPn + y) * KQn;
        const uint4* fk4 = reinterpret_cast<const uint4*>(g_fk + base * Tn);
        for (int i = tid; i < 192 * 8; i += 192) {
            const int row = i >> 3, f4 = i & 7;
            uint4 w = fk4[i];
            uint32_t* dk = sfk + row * SPAD + f4 * 4;
            dk[0] = w.x; dk[1] = w.y; dk[2] = w.z; dk[3] = w.w;
        }
        sbv[tid] = make_float2((mask[base + tid] < 0.5f) ? NEGV : 0.f, g_vw[base + tid]);

        // fq fragments straight from global (rows contiguous)
        #pragma unroll
        for (int ks = 0; ks < 4; ks++)
            #pragma unroll
            for (int mt = 0; mt < 2; mt++) {
                const int r = base + m0 + mt * 16;
                aF[ks][mt][0] = fqg[(r + g) * Tn + ks * 8 + t4];
                aF[ks][mt][1] = fqg[(r + g + 8) * Tn + ks * 8 + t4];
                aF[ks][mt][2] = fqg[(r + g) * Tn + ks * 8 + t4 + 4];
                aF[ks][mt][3] = fqg[(r + g + 8) * Tn + ks * 8 + t4 + 4];
            }
        __syncthreads();

        float s[4], t[4]; int rows[4];
        attn_mma_core(aF, sfk, sbv, tid, s, t, rows);
        if ((tid & 3) == 0) {
            #pragma unroll
            for (int i = 0; i < 4; i++) g_Umh[base + rows[i]] = t[i] / s[i];
        }
    } else {
        const int q = y;
        const uint4* fkg = reinterpret_cast<const uint4*>(g_fk);
        for (int i = tid; i < 192 * 8; i += 192) {
            const int row = i >> 3, f4 = i & 7;
            uint4 w = fkg[((b * KPn + row) * KQn + q) * 8 + f4];
            uint32_t* dk = sfk + row * SPAD + f4 * 4;
            dk[0] = w.x; dk[1] = w.y; dk[2] = w.z; dk[3] = w.w;
        }
        {
            const int idx = (b * KPn + tid) * KQn + q;
            sbv[tid] = make_float2((mask[idx] < 0.5f) ? NEGV : 0.f, g_vw[idx]);
        }

        // fq fragments from global (strided rows; 128B-contiguous per row)
        #pragma unroll
        for (int ks = 0; ks < 4; ks++)
            #pragma unroll
            for (int mt = 0; mt < 2; mt++) {
                const int r = m0 + mt * 16;
                const int i0 = ((b * KPn + r + g) * KQn + q) * Tn;
                const int i1 = ((b * KPn + r + g + 8) * KQn + q) * Tn;
                aF[ks][mt][0] = fqg[i0 + ks * 8 + t4];
                aF[ks][mt][1] = fqg[i1 + ks * 8 + t4];
                aF[ks][mt][2] = fqg[i0 + ks * 8 + t4 + 4];
                aF[ks][mt][3] = fqg[i1 + ks * 8 + t4 + 4];
            }
        __syncthreads();

        float s[4], t[4]; int rows[4];
        attn_mma_core(aF, sfk, sbv, tid, s, t, rows);
        if ((tid & 3) == 0) {
            #pragma unroll
            for (int i = 0; i < 4; i++)
                g_Umv[(b * KPn + rows[i]) * KQn + q] = t[i] / s[i];
        }
    }
}

// ---------------- K4: U via tf32 MMA, 64x32 tiles (72 blocks) ----------------
__global__ __launch_bounds__(256) void k4_U(
    const float* __restrict__ Eq, const float* __restrict__ Ep,
    const float* __restrict__ W_out, const float* __restrict__ mask)
{
    __shared__ uint32_t sA[64 * 36];
    __shared__ uint32_t sB[32 * 36];
    __shared__ float sw3[Hn];

    const int b = blockIdx.z;
    const int row0 = blockIdx.y * 64;   // p
    const int col0 = blockIdx.x * 32;   // q
    const int tid = threadIdx.x;
    const int wid = tid >> 5, lane = tid & 31, g = lane >> 2, t4 = lane & 3;
    const int wr = wid & 1, wc = wid >> 1;
    float c[2][4] = {};

    for (int i = tid; i < Hn; i += 256) sw3[i] = W_out[2 * Hn + i];
    __syncthreads();

    for (int kc = 0; kc < Hn; kc += 32) {
        #pragma unroll
        for (int h = 0; h < 2; h++) {
            const int i = tid + h * 256;
            const int r = i >> 3, j4 = i & 7;
            float4 av = *reinterpret_cast<const float4*>(Ep + (b * KPn + row0 + r) * Hn + kc + j4 * 4);
            uint32_t* da = sA + r * 36 + j4 * 4;
            da[0] = tf32cvt(av.x); da[1] = tf32cvt(av.y); da[2] = tf32cvt(av.z); da[3] = tf32cvt(av.w);
        }
        {
            const int r = tid >> 3, j4 = tid & 7;
            float4 bv = *reinterpret_cast<const float4*>(Eq + (b * KQn + col0 + r) * Hn + kc + j4 * 4);
            uint32_t* db = sB + r * 36 + j4 * 4;
            db[0] = tf32cvt(bv.x * sw3[kc + j4 * 4 + 0]);
            db[1] = tf32cvt(bv.y * sw3[kc + j4 * 4 + 1]);
            db[2] = tf32cvt(bv.z * sw3[kc + j4 * 4 + 2]);
            db[3] = tf32cvt(bv.w * sw3[kc + j4 * 4 + 3]);
        }
        __syncthreads();
        #pragma unroll
        for (int ks = 0; ks < 4; ks++) {
            uint32_t a[2][4];
            #pragma unroll
            for (int mt = 0; mt < 2; mt++) {
                const int r = wr * 32 + mt * 16;
                a[mt][0] = sA[(r + g) * 36 + ks * 8 + t4];
                a[mt][1] = sA[(r + g + 8) * 36 + ks * 8 + t4];
                a[mt][2] = sA[(r + g) * 36 + ks * 8 + t4 + 4];
                a[mt][3] = sA[(r + g + 8) * 36 + ks * 8 + t4 + 4];
            }
            const uint32_t b0 = sB[(wc * 8 + g) * 36 + ks * 8 + t4];
            const uint32_t b1 = sB[(wc * 8 + g) * 36 + ks * 8 + t4 + 4];
            mma_tf32(c[0], a[0], b0, b1);
            mma_tf32(c[1], a[1], b0, b1);
        }
        __syncthreads();
    }

    #pragma unroll
    for (int mt = 0; mt < 2; mt++)
        #pragma unroll
        for (int half = 0; half < 2; half++) {
            const int row = row0 + wr * 32 + mt * 16 + g + half * 8;
            const int col = col0 + wc * 8 + 2 * t4;
            const int idx = (b * KPn + row) * KQn + col;
            const float u2v = g_u2[b * KPn + row];
            float U0 = c[mt][half * 2 + 0] + g_u1[b * KQn + col] + u2v + g_Umh[idx] + g_Umv[idx];
            float U1 = c[mt][half * 2 + 1] + g_u1[b * KQn + col + 1] + u2v + g_Umh[idx + 1] + g_Umv[idx + 1];
            if (mask[idx] < 0.5f) U0 = NEGV;
            if (mask[idx + 1] < 0.5f) U1 = NEGV;
            *reinterpret_cast<float2*>(g_U + idx) = make_float2(U0, U1);
        }
}

// ---------------- K5: both softmax aggregations (z = dir), merged ----------------
__global__ __launch_bounds__(256) void k5_soft(const float* __restrict__ Eq, const float* __restrict__ Ep)
{
    const int b = blockIdx.x, y = blockIdx.y, dir = blockIdx.z;
    __shared__ float sw[192];
    __shared__ float red[256];
    const int tid = threadIdx.x;

    float v;
    if (dir == 0) v = (tid < KQn) ? g_U[(b * KPn + y) * KQn + tid] : -3.4e38f;
    else          v = (tid < KPn) ? g_U[(b * KPn + tid) * KQn + y] : -3.4e38f;
    red[tid] = v; __syncthreads();
    for (int o = 128; o; o >>= 1) { if (tid < o) red[tid] = fmaxf(red[tid], red[tid + o]); __syncthreads(); }
    const float m = red[0]; __syncthreads();
    const float e = (tid < 192) ? __expf(v - m) : 0.f;
    red[tid] = e; __syncthreads();
    for (int o = 128; o; o >>= 1) { if (tid < o) red[tid] += red[tid + o]; __syncthreads(); }
    const float inv = 1.f / red[0];
    if (tid < 192) sw[tid] = e * inv;
    __syncthreads();

    const int h = tid;
    float a0 = 0.f, a1 = 0.f;
    if (dir == 0) {
        for (int k = 0; k < KQn; k += 2) {
            a0 += sw[k] * Eq[(b * KQn + k) * Hn + h];
            a1 += sw[k + 1] * Eq[(b * KQn + k + 1) * Hn + h];
        }
        const float a = a0 + a1;
        const float ep = Ep[(b * KPn + y) * Hn + h];
        float* G = g_Gl + (b * KPn + y) * Rn;
        G[h] = ep; G[Hn + h] = a; G[2 * Hn + h] = ep * a;
    } else {
        for (int k = 0; k < KPn; k += 2) {
            a0 += sw[k] * Ep[(b * KPn + k) * Hn + h];
            a1 += sw[k + 1] * Ep[(b * KPn + k + 1) * Hn + h];
        }
        const float a = a0 + a1;
        const float eq = Eq[(b * KQn + y) * Hn + h];
        float* G = g_Gr + (b * KQn + y) * Rn;
        G[h] = eq; G[Hn + h] = a; G[2 * Hn + h] = eq * a;
    }
}

// ---------------- K6: gates via tf32 MMA, 64x64 tile ----------------
__global__ __launch_bounds__(256) void k6_gate(
    const float* __restrict__ Wl, const float* __restrict__ bl,
    const float* __restrict__ Wr, const float* __restrict__ br)
{
    __shared__ uint32_t sG[64 * 36];
    __shared__ uint32_t sW[64 * 36];

    const int side = blockIdx.z;
    const float* __restrict__ G = side ? g_Gr : g_Gl;
    const float* __restrict__ W = side ? Wr : Wl;
    const float* __restrict__ bias = side ? br : bl;
    float* __restrict__ outp = side ? g_right : g_left;
    const int row0 = blockIdx.y * 64;
    const int col0 = blockIdx.x * 64;

    const int tid = threadIdx.x;
    const int wid = tid >> 5, lane = tid & 31, g = lane >> 2, t4 = lane & 3;
    const int wr = wid >> 2, wc = wid & 3;
    float c[2][2][4] = {};

    for (int kc = 0; kc < Rn; kc += 32) {
        #pragma unroll
        for (int h = 0; h < 2; h++) {
            const int i = tid + h * 256;
            const int r = i >> 3, j4 = i & 7;
            float4 gv = *reinterpret_cast<const float4*>(G + (row0 + r) * Rn + kc + j4 * 4);
            uint32_t* dg = sG + r * 36 + j4 * 4;
            dg[0] = tf32cvt(gv.x); dg[1] = tf32cvt(gv.y); dg[2] = tf32cvt(gv.z); dg[3] = tf32cvt(gv.w);
            float4 wv = *reinterpret_cast<const float4*>(W + (col0 + r) * Rn + kc + j4 * 4);
            uint32_t* dw = sW + r * 36 + j4 * 4;
            dw[0] = tf32cvt(wv.x); dw[1] = tf32cvt(wv.y); dw[2] = tf32cvt(wv.z); dw[3] = tf32cvt(wv.w);
        }
        __syncthreads();
        #pragma unroll
        for (int ks = 0; ks < 4; ks++) {
            uint32_t a[2][4];
            #pragma unroll
            for (int mt = 0; mt < 2; mt++) {
                const int r = wr * 32 + mt * 16;
                a[mt][0] = sG[(r + g) * 36 + ks * 8 + t4];
                a[mt][1] = sG[(r + g + 8) * 36 + ks * 8 + t4];
                a[mt][2] = sG[(r + g) * 36 + ks * 8 + t4 + 4];
                a[mt][3] = sG[(r + g + 8) * 36 + ks * 8 + t4 + 4];
            }
            #pragma unroll
            for (int nt = 0; nt < 2; nt++) {
                const uint32_t b0 = sW[(wc * 16 + nt * 8 + g) * 36 + ks * 8 + t4];
                const uint32_t b1 = sW[(wc * 16 + nt * 8 + g) * 36 + ks * 8 + t4 + 4];
                mma_tf32(c[0][nt], a[0], b0, b1);
                mma_tf32(c[1][nt], a[1], b0, b1);
            }
        }
        __syncthreads();
    }

    #pragma unroll
    for (int mt = 0; mt < 2; mt++)
        #pragma unroll
        for (int nt = 0; nt < 2; nt++) {
            const int row = row0 + wr * 32 + mt * 16 + g;
            const int col = col0 + wc * 16 + nt * 8 + 2 * t4;
            const float b0f = bias[col], b1f = bias[col + 1];
            {
                float2 gv = *reinterpret_cast<const float2*>(G + row * Rn + col);
                const float s0 = 1.f / (1.f + __expf(-(c[mt][nt][0] + b0f)));
                const float s1 = 1.f / (1.f + __expf(-(c[mt][nt][1] + b1f)));
                *reinterpret_cast<float2*>(outp + row * Rn + col) = make_float2(s0 * gv.x, s1 * gv.y);
            }
            {
                float2 gv = *reinterpret_cast<const float2*>(G + (row + 8) * Rn + col);
                const float s2 = 1.f / (1.f + __expf(-(c[mt][nt][2] + b0f)));
                const float s3 = 1.f / (1.f + __expf(-(c[mt][nt][3] + b1f)));
                *reinterpret_cast<float2*>(outp + (row + 8) * Rn + col) = make_float2(s2 * gv.x, s3 * gv.y);
            }
        }
}

// ---------------- K7: split-K partials via 3-term split-tf32 MMA ----------------
__global__ __launch_bounds__(256) void k7_partial()
{
    __shared__ uint32_t hA[64 * 36], lA[64 * 36], hB[64 * 36], lB[64 * 36];

    const int z = blockIdx.z;
    const int b = z >> 2, ksz = z & 3;
    const int kbase = ksz * 192;
    const float* __restrict__ A = g_left + b * KPn * Rn;
    const float* __restrict__ Bm = g_right + b * KQn * Rn;
    const int row0 = blockIdx.y * 64;
    const int col0 = blockIdx.x * 64;
    const int tid = threadIdx.x;
    const int wid = tid >> 5, lane = tid & 31, g = lane >> 2, t4 = lane & 3;
    const int wr = wid >> 2, wc = wid & 3;
    float c[2][2][4] = {};

    for (int kc = kbase; kc < kbase + 192; kc += 32) {
        #pragma unroll
        for (int h = 0; h < 2; h++) {
            const int i = tid + h * 256;
            const int r = i >> 3, j4 = i & 7;
            float4 av = *reinterpret_cast<const float4*>(A + (row0 + r) * Rn + kc + j4 * 4);
            float4 bv = *reinterpret_cast<const float4*>(Bm + (col0 + r) * Rn + kc + j4 * 4);
            #pragma unroll
            for (int e = 0; e < 4; e++) {
                const float xa = (&av.x)[e];
                const uint32_t ha = tf32cvt(xa);
                hA[r * 36 + j4 * 4 + e] = ha;
                lA[r * 36 + j4 * 4 + e] = tf32cvt(xa - __uint_as_float(ha));
                const float xb = (&bv.x)[e];
                const uint32_t hb = tf32cvt(xb);
                hB[r * 36 + j4 * 4 + e] = hb;
                lB[r * 36 + j4 * 4 + e] = tf32cvt(xb - __uint_as_float(hb));
            }
        }
        __syncthreads();
        #pragma unroll
        for (int ks = 0; ks < 4; ks++) {
            uint32_t aH[2][4], aL[2][4];
            #pragma unroll
            for (int mt = 0; mt < 2; mt++) {
                const int r = wr * 32 + mt * 16;
                aH[mt][0] = hA[(r + g) * 36 + ks * 8 + t4];
                aH[mt][1] = hA[(r + g + 8) * 36 + ks * 8 + t4];
                aH[mt][2] = hA[(r + g) * 36 + ks * 8 + t4 + 4];
                aH[mt][3] = hA[(r + g + 8) * 36 + ks * 8 + t4 + 4];
                aL[mt][0] = lA[(r + g) * 36 + ks * 8 + t4];
                aL[mt][1] = lA[(r + g + 8) * 36 + ks * 8 + t4];
                aL[mt][2] = lA[(r + g) * 36 + ks * 8 + t4 + 4];
                aL[mt][3] = lA[(r + g + 8) * 36 + ks * 8 + t4 + 4];
            }
            #pragma unroll
            for (int nt = 0; nt < 2; nt++) {
                const int rb = wc * 16 + nt * 8 + g;
                const uint32_t bh0 = hB[rb * 36 + ks * 8 + t4];
                const uint32_t bh1 = hB[rb * 36 + ks * 8 + t4 + 4];
                const uint32_t bl0 = lB[rb * 36 + ks * 8 + t4];
                const uint32_t bl1 = lB[rb * 36 + ks * 8 + t4 + 4];
                #pragma unroll
                for (int mt = 0; mt < 2; mt++) {
                    mma_tf32(c[mt][nt], aH[mt], bh0, bh1);
                    mma_tf32(c[mt][nt], aH[mt], bl0, bl1);
                    mma_tf32(c[mt][nt], aL[mt], bh0, bh1);
                }
            }
        }
        __syncthreads();
    }

    float* dst = g_part + ksz * (BB * KPn * KQn) + b * (KPn * KQn);
    #pragma unroll
    for (int mt = 0; mt < 2; mt++)
        #pragma unroll
        for (int nt = 0; nt < 2; nt++)
            #pragma unroll
            for (int half = 0; half < 2; half++) {
                const int row = row0 + wr * 32 + mt * 16 + g + half * 8;
                const int col = col0 + wc * 16 + nt * 8 + 2 * t4;
                *reinterpret_cast<float2*>(dst + row * KQn + col) =
                    make_float2(c[mt][nt][half * 2 + 0], c[mt][nt][half * 2 + 1]);
            }
}

// ---------------- K8: reduce split-K + relu ----------------
__global__ __launch_bounds__(256) void k8_reduce(float* __restrict__ outp)
{
    const int idx = blockIdx.x * 256 + threadIdx.x;
    const int n = BB * KPn * KQn;
    if (idx < n) {
        float s = (g_part[idx] + g_part[n + idx]) + (g_part[2 * n + idx] + g_part[3 * n + idx]);
        outp[idx] = fmaxf(s, 0.f);
    }
}

// ---------------- launch ----------------
extern "C" void kernel_launch(void* const* d_in, const int* in_sizes, int n_in,
                              void* d_out, int out_size)
{
    const float* Eq    = (const float*)d_in[0];
    const float* Ep    = (const float*)d_in[1];
    const float* mask  = (const float*)d_in[2];
    const float* W_in  = (const float*)d_in[3];
    const float* Wq    = (const float*)d_in[4];
    const float* bq    = (const float*)d_in[5];
    const float* Wk    = (const float*)d_in[6];
    const float* bk    = (const float*)d_in[7];
    const float* Wv    = (const float*)d_in[8];
    const float* bv    = (const float*)d_in[9];
    const float* Wo1   = (const float*)d_in[10];
    const float* bo1   = (const float*)d_in[11];
    const float* Wo2   = (const float*)d_in[12];
    const float* bo2   = (const float*)d_in[13];
    const float* W_out = (const float*)d_in[14];
    const float* Wl    = (const float*)d_in[15];
    const float* bl    = (const float*)d_in[16];
    const float* Wr    = (const float*)d_in[17];
    const float* br    = (const float*)d_in[18];
    float* outp = (float*)d_out;

    const int smemAttn = 192 * SPAD * 4 + 192 * 8;                     // 29184 B
    const int smemK1 = (32 * 260 + 192 * 36) * 4 + (Hn + Tn) * 4;      // 62080 B
    cudaFuncSetAttribute(k23_attn, cudaFuncAttributeMaxDynamicSharedMemorySize, smemAttn);
    cudaFuncSetAttribute(k1_pair, cudaFuncAttributeMaxDynamicSharedMemorySize, smemK1);

    k0_rowproj<<<dim3(BB, 2, 4), dim3(32, 8)>>>(Eq, Ep, W_in, W_out);
    k0b_wv4<<<1, 32>>>(Wv, bv, W_out);
    k1_pair<<<dim3(BB, KPn), 192, smemK1>>>(Eq, Ep, W_in, Wq, bq, Wk, bk, Wo1, bo1, Wo2, bo2);
    k23_attn<<<dim3(BB, 192, 2), 192, smemAttn>>>(mask);
    k4_U<<<dim3(6, 3, BB), 256>>>(Eq, Ep, W_out, mask);
    k5_soft<<<dim3(BB, 192, 2), 256>>>(Eq, Ep);
    k6_gate<<<dim3(12, 12, 2), 256>>>(Wl, bl, Wr, br);
    k7_partial<<<dim3(3, 3, 16), 256>>>();
    k8_reduce<<<dim3(576), 256>>>(outp);
}

// round 15
// speedup vs baseline: 1.0882x; 1.0882x over previous
#include <cuda_runtime.h>
#include <cuda_bf16.h>
#include <math.h>
#include <stdint.h>

#define BB 4
#define KQn 192
#define KPn 192
#define Hn 256
#define Tn 32
#define Rn 768
#define NEGV (-1e9f)
#define SCALEV (0.17677669529663687f)   // 1/sqrt(32)
#define SPADH 18                         // bf16 smem row stride in u32 words

// ---------------- scratch ----------------
static __device__ float g_A1[BB * KQn * Tn];
static __device__ float g_A2[BB * KPn * Tn];
static __device__ float g_u1[BB * KQn];
static __device__ float g_u2[BB * KPn];
static __device__ uint32_t g_fq[BB * KPn * KQn * 16];  // bf16x2 packed, 32 vals/row
static __device__ uint32_t g_fk[BB * KPn * KQn * 16];  // bf16x2 packed, pre-scaled by obv*SCALE
static __device__ float g_vw[BB * KPn * KQn];
static __device__ float g_wv4[Tn];
static __device__ float g_c0[1];
static __device__ float g_Umh[BB * KPn * KQn];
static __device__ float g_Umv[BB * KPn * KQn];
static __device__ float g_U[BB * KPn * KQn];
static __device__ float g_Gl[BB * KPn * Rn];
static __device__ float g_Gr[BB * KQn * Rn];
static __device__ float g_left[BB * KPn * Rn];
static __device__ float g_right[BB * KQn * Rn];
static __device__ float g_part[4 * BB * KPn * KQn];

__device__ __forceinline__ uint32_t tf32cvt(float x) {
    uint32_t u;
    asm("cvt.rna.tf32.f32 %0, %1;" : "=r"(u) : "f"(x));
    return u;
}

__device__ __forceinline__ uint32_t packbf(float lo, float hi) {
    __nv_bfloat162 h = __floats2bfloat162_rn(lo, hi);
    return *reinterpret_cast<uint32_t*>(&h);
}

__device__ __forceinline__ void mma_tf32(float c[4], const uint32_t a[4], uint32_t b0, uint32_t b1) {
    asm volatile("mma.sync.aligned.m16n8k8.row.col.f32.tf32.tf32.f32 "
        "{%0,%1,%2,%3}, {%4,%5,%6,%7}, {%8,%9}, {%0,%1,%2,%3};"
        : "+f"(c[0]), "+f"(c[1]), "+f"(c[2]), "+f"(c[3])
        : "r"(a[0]), "r"(a[1]), "r"(a[2]), "r"(a[3]), "r"(b0), "r"(b1));
}

__device__ __forceinline__ void mma_bf16(float c[4], const uint32_t a[4], uint32_t b0, uint32_t b1) {
    asm volatile("mma.sync.aligned.m16n8k16.row.col.f32.bf16.bf16.f32 "
        "{%0,%1,%2,%3}, {%4,%5,%6,%7}, {%8,%9}, {%0,%1,%2,%3};"
        : "+f"(c[0]), "+f"(c[1]), "+f"(c[2]), "+f"(c[3])
        : "r"(a[0]), "r"(a[1]), "r"(a[2]), "r"(a[3]), "r"(b0), "r"(b1));
}

// ---------------- K0: per-row projections A1/A2 and u1/u2 ----------------
__global__ __launch_bounds__(256) void k0_rowproj(
    const float* __restrict__ Eq, const float* __restrict__ Ep,
    const float* __restrict__ W_in, const float* __restrict__ W_out)
{
    const int b = blockIdx.x;
    const int side = blockIdx.y;
    const float* src = side ? (Ep + b * KPn * Hn) : (Eq + b * KQn * Hn);
    const int woff = side ? Hn : 0;
    float* A = side ? (g_A2 + b * KPn * Tn) : (g_A1 + b * KQn * Tn);
    float* u = side ? (g_u2 + b * KPn) : (g_u1 + b * KQn);

    __shared__ float sW[Tn][Hn + 1];
    __shared__ float swv[Hn];
    const int tid = threadIdx.y * 32 + threadIdx.x;
    for (int i = tid; i < Tn * Hn; i += 256) {
        int t = i >> 8, h = i & 255;
        sW[t][h] = W_in[t * Rn + woff + h];
    }
    for (int i = tid; i < Hn; i += 256) swv[i] = W_out[woff + i];
    __syncthreads();

    const int t = threadIdx.x;
    const int y0 = blockIdx.z * 48;
    for (int y = y0 + threadIdx.y; y < y0 + 48; y += 8) {
        const float* row = src + y * Hn;
        float p0 = 0.f, p1 = 0.f, p2 = 0.f, p3 = 0.f, up = 0.f;
        for (int h = 0; h < Hn; h += 4) {
            p0 += row[h] * sW[t][h];
            p1 += row[h + 1] * sW[t][h + 1];
            p2 += row[h + 2] * sW[t][h + 2];
            p3 += row[h + 3] * sW[t][h + 3];
        }
        for (int h = t; h < Hn; h += 32) up += row[h] * swv[h];
        #pragma unroll
        for (int o = 16; o; o >>= 1) up += __shfl_down_sync(0xffffffffu, up, o);
        A[y * Tn + t] = (p0 + p1) + (p2 + p3);
        if (t == 0) u[y] = up;
    }
}

// ---------------- K0b: wv4 = Wv^T @ w4, c0 = bv . w4 ----------------
__global__ void k0b_wv4(const float* __restrict__ Wv, const float* __restrict__ bv,
                        const float* __restrict__ W_out)
{
    const int t = threadIdx.x;
    float s = 0.f;
    for (int u = 0; u < Tn; u++) s += Wv[u * Tn + t] * W_out[Rn + u];
    g_wv4[t] = s;
    float c = bv[t] * W_out[Rn + t];
    #pragma unroll
    for (int o = 16; o; o >>= 1) c += __shfl_down_sync(0xffffffffu, c, o);
    if (t == 0) g_c0[0] = c;
}

// ---------------- K1: bilinear MMA -> E1 -> projection MMA; bf16 fq/fk output ----------------
__global__ __launch_bounds__(192) void k1_pair(
    const float* __restrict__ Eq, const float* __restrict__ Ep,
    const float* __restrict__ W_in,
    const float* __restrict__ Wq, const float* __restrict__ bq,
    const float* __restrict__ Wk, const float* __restrict__ bk,
    const float* __restrict__ Wo1, const float* __restrict__ bo1,
    const float* __restrict__ Wo2, const float* __restrict__ bo2)
{
    extern __shared__ uint32_t smem[];
    uint32_t* sW3 = smem;                                   // 32*260 (>= 104*36)
    uint32_t* sA = sW3 + 32 * 260;                          // 192*36
    float* sE1f = reinterpret_cast<float*>(sA);
    float* sEpRow = reinterpret_cast<float*>(sA + 192 * 36);
    float* sA2 = sEpRow + Hn;

    const int b = blockIdx.x, p = blockIdx.y;
    const int tid = threadIdx.x;
    const int wid = tid >> 5, lane = tid & 31, g = lane >> 2, t4 = lane & 3;
    const int m0 = wid * 32;

    for (int i = tid; i < 32 * 64; i += 192) {
        const int t = i >> 6, h4 = i & 63;
        float4 w = reinterpret_cast<const float4*>(W_in + t * Rn + 2 * Hn)[h4];
        uint32_t* d = sW3 + t * 260 + h4 * 4;
        d[0] = tf32cvt(w.x); d[1] = tf32cvt(w.y); d[2] = tf32cvt(w.z); d[3] = tf32cvt(w.w);
    }
    for (int i = tid; i < Hn / 4; i += 192)
        reinterpret_cast<float4*>(sEpRow)[i] =
            reinterpret_cast<const float4*>(Ep + (b * KPn + p) * Hn)[i];
    if (tid < Tn) sA2[tid] = g_A2[(b * KPn + p) * Tn + tid];
    __syncthreads();

    // ---- stage 1: bilinear E1 = (Eq o Ep) @ W3^T (warp-local A tiles) ----
    float c1[2][4][4] = {};
    const float4* eqrow = reinterpret_cast<const float4*>(Eq + (b * KQn + tid) * Hn);
    const float4* sEpRow4 = reinterpret_cast<const float4*>(sEpRow);

    for (int kc = 0; kc < 8; kc++) {
        #pragma unroll
        for (int j = 0; j < 8; j++) {
            float4 e = eqrow[kc * 8 + j];
            float4 pp = sEpRow4[kc * 8 + j];
            uint32_t* d = sA + tid * 36 + j * 4;
            d[0] = tf32cvt(e.x * pp.x); d[1] = tf32cvt(e.y * pp.y);
            d[2] = tf32cvt(e.z * pp.z); d[3] = tf32cvt(e.w * pp.w);
        }
        __syncwarp();
        #pragma unroll
        for (int ks = 0; ks < 4; ks++) {
            uint32_t a[2][4];
            #pragma unroll
            for (int mt = 0; mt < 2; mt++) {
                const int r = m0 + mt * 16;
                a[mt][0] = sA[(r + g) * 36 + ks * 8 + t4];
                a[mt][1] = sA[(r + g + 8) * 36 + ks * 8 + t4];
                a[mt][2] = sA[(r + g) * 36 + ks * 8 + t4 + 4];
                a[mt][3] = sA[(r + g + 8) * 36 + ks * 8 + t4 + 4];
            }
            #pragma unroll
            for (int nt = 0; nt < 4; nt++) {
                const uint32_t b0 = sW3[(nt * 8 + g) * 260 + kc * 32 + ks * 8 + t4];
                const uint32_t b1 = sW3[(nt * 8 + g) * 260 + kc * 32 + ks * 8 + t4 + 4];
                mma_tf32(c1[0][nt], a[0], b0, b1);
                mma_tf32(c1[1][nt], a[1], b0, b1);
            }
        }
        __syncwarp();
    }

    #pragma unroll
    for (int mt = 0; mt < 2; mt++)
        #pragma unroll
        for (int nt = 0; nt < 4; nt++) {
            const int r0 = m0 + mt * 16 + g;
            const int col = nt * 8 + 2 * t4;
            sE1f[r0 * 36 + col] = c1[mt][nt][0];
            sE1f[r0 * 36 + col + 1] = c1[mt][nt][1];
            sE1f[(r0 + 8) * 36 + col] = c1[mt][nt][2];
            sE1f[(r0 + 8) * 36 + col + 1] = c1[mt][nt][3];
        }
    __syncwarp();

    {
        const int q = tid;
        const float4* a1 = reinterpret_cast<const float4*>(g_A1 + (b * KQn + q) * Tn);
        #pragma unroll
        for (int i4 = 0; i4 < 8; i4++) {
            float4 ev = *reinterpret_cast<const float4*>(&sE1f[q * 36 + i4 * 4]);
            float4 a = a1[i4];
            uint32_t* d = sA + q * 36 + i4 * 4;
            d[0] = tf32cvt(ev.x + a.x + sA2[i4 * 4 + 0]);
            d[1] = tf32cvt(ev.y + a.y + sA2[i4 * 4 + 1]);
            d[2] = tf32cvt(ev.z + a.z + sA2[i4 * 4 + 2]);
            d[3] = tf32cvt(ev.w + a.w + sA2[i4 * 4 + 3]);
        }
    }
    __syncthreads();

    for (int i = tid; i < 96 * 32; i += 192) {
        const int n = i >> 5, t = i & 31;
        float w = (n < 32) ? Wo1[n * 32 + t] : (n < 64) ? Wq[(n - 32) * 32 + t] : Wk[(n - 64) * 32 + t];
        sW3[n * 36 + t] = tf32cvt(w);
    }
    if (tid < 32) sW3[96 * 36 + tid] = tf32cvt(g_wv4[tid]);
    for (int i = tid; i < 7 * 36; i += 192) sW3[97 * 36 + i] = 0u;
    __syncthreads();

    const int pairbase = (b * KPn + p) * KQn;
    const float bo2v = bo2[0];
    const float c0v = g_c0[0];
    float scReg[4];

    // G0: Wo1 -> sc
    {
        float c[2][4][4] = {};
        #pragma unroll
        for (int ks = 0; ks < 4; ks++) {
            uint32_t a[2][4];
            #pragma unroll
            for (int mt = 0; mt < 2; mt++) {
                const int r = m0 + mt * 16;
                a[mt][0] = sA[(r + g) * 36 + ks * 8 + t4];
                a[mt][1] = sA[(r + g + 8) * 36 + ks * 8 + t4];
                a[mt][2] = sA[(r + g) * 36 + ks * 8 + t4 + 4];
                a[mt][3] = sA[(r + g + 8) * 36 + ks * 8 + t4 + 4];
            }
            #pragma unroll
            for (int nt = 0; nt < 4; nt++) {
                const uint32_t b0 = sW3[(nt * 8 + g) * 36 + ks * 8 + t4];
                const uint32_t b1 = sW3[(nt * 8 + g) * 36 + ks * 8 + t4 + 4];
                mma_tf32(c[0][nt], a[0], b0, b1);
                mma_tf32(c[1][nt], a[1], b0, b1);
            }
        }
        #pragma unroll
        for (int mt = 0; mt < 2; mt++)
            #pragma unroll
            for (int half = 0; half < 2; half++) {
                float part = 0.f;
                #pragma unroll
                for (int nt = 0; nt < 4; nt++) {
                    const int col = nt * 8 + 2 * t4;
                    part += fmaxf(c[mt][nt][half * 2 + 0] + bo1[col], 0.f) * Wo2[col]
                          + fmaxf(c[mt][nt][half * 2 + 1] + bo1[col + 1], 0.f) * Wo2[col + 1];
                }
                part += __shfl_xor_sync(0xffffffffu, part, 1);
                part += __shfl_xor_sync(0xffffffffu, part, 2);
                scReg[mt * 2 + half] = SCALEV / (1.f + __expf(-(part + bo2v)));
            }
    }

    // G1: Wq -> g_fq (bf16 packed)
    {
        float c[2][4][4] = {};
        #pragma unroll
        for (int ks = 0; ks < 4; ks++) {
            uint32_t a[2][4];
            #pragma unroll
            for (int mt = 0; mt < 2; mt++) {
                const int r = m0 + mt * 16;
                a[mt][0] = sA[(r + g) * 36 + ks * 8 + t4];
                a[mt][1] = sA[(r + g + 8) * 36 + ks * 8 + t4];
                a[mt][2] = sA[(r + g) * 36 + ks * 8 + t4 + 4];
                a[mt][3] = sA[(r + g + 8) * 36 + ks * 8 + t4 + 4];
            }
            #pragma unroll
            for (int nt = 0; nt < 4; nt++) {
                const uint32_t b0 = sW3[(32 + nt * 8 + g) * 36 + ks * 8 + t4];
                const uint32_t b1 = sW3[(32 + nt * 8 + g) * 36 + ks * 8 + t4 + 4];
                mma_tf32(c[0][nt], a[0], b0, b1);
                mma_tf32(c[1][nt], a[1], b0, b1);
            }
        }
        #pragma unroll
        for (int mt = 0; mt < 2; mt++)
            #pragma unroll
            for (int nt = 0; nt < 4; nt++) {
                const int r0 = m0 + mt * 16 + g;
                const int w = nt * 4 + t4;                 // word index (col/2)
                const int col = nt * 8 + 2 * t4;
                const float b0f = bq[col], b1f = bq[col + 1];
                g_fq[(pairbase + r0) * 16 + w]     = packbf(c[mt][nt][0] + b0f, c[mt][nt][1] + b1f);
                g_fq[(pairbase + r0 + 8) * 16 + w] = packbf(c[mt][nt][2] + b0f, c[mt][nt][3] + b1f);
            }
    }

    // G2: Wk + wv4 -> g_fk (bf16 packed, scaled) + g_vw
    {
        float c[2][5][4] = {};
        #pragma unroll
        for (int ks = 0; ks < 4; ks++) {
            uint32_t a[2][4];
            #pragma unroll
            for (int mt = 0; mt < 2; mt++) {
                const int r = m0 + mt * 16;
                a[mt][0] = sA[(r + g) * 36 + ks * 8 + t4];
                a[mt][1] = sA[(r + g + 8) * 36 + ks * 8 + t4];
                a[mt][2] = sA[(r + g) * 36 + ks * 8 + t4 + 4];
                a[mt][3] = sA[(r + g + 8) * 36 + ks * 8 + t4 + 4];
            }
            #pragma unroll
            for (int nt = 0; nt < 5; nt++) {
                const uint32_t b0 = sW3[(64 + nt * 8 + g) * 36 + ks * 8 + t4];
                const uint32_t b1 = sW3[(64 + nt * 8 + g) * 36 + ks * 8 + t4 + 4];
                mma_tf32(c[0][nt], a[0], b0, b1);
                mma_tf32(c[1][nt], a[1], b0, b1);
            }
        }
        #pragma unroll
        for (int mt = 0; mt < 2; mt++)
            #pragma unroll
            for (int nt = 0; nt < 4; nt++) {
                const int r0 = m0 + mt * 16 + g;
                const int w = nt * 4 + t4;
                const int col = nt * 8 + 2 * t4;
                const float b0f = bk[col], b1f = bk[col + 1];
                const float s0 = scReg[mt * 2 + 0], s1 = scReg[mt * 2 + 1];
                g_fk[(pairbase + r0) * 16 + w]     = packbf((c[mt][nt][0] + b0f) * s0, (c[mt][nt][1] + b1f) * s0);
                g_fk[(pairbase + r0 + 8) * 16 + w] = packbf((c[mt][nt][2] + b0f) * s1, (c[mt][nt][3] + b1f) * s1);
            }
        if (t4 == 0) {
            #pragma unroll
            for (int mt = 0; mt < 2; mt++) {
                const int r0 = m0 + mt * 16 + g;
                g_vw[pairbase + r0] = c[mt][4][0] + c0v;
                g_vw[pairbase + r0 + 8] = c[mt][4][2] + c0v;
            }
        }
    }
}

// ================= bf16 tensor-core attention core =================
__device__ __forceinline__ void attn_mma_core(
    const uint32_t* __restrict__ sfq, const uint32_t* __restrict__ sfk,
    const float2* __restrict__ sbv, int tid, float sOut[4], float tOut[4], int rows[4])
{
    const int wid = tid >> 5, lane = tid & 31;
    const int g = lane >> 2, t4 = lane & 3;
    const int m0 = wid * 32;

    uint32_t aF[2][2][4];   // [ks][mt]
    #pragma unroll
    for (int ks = 0; ks < 2; ks++)
        #pragma unroll
        for (int mt = 0; mt < 2; mt++) {
            const int r = m0 + mt * 16;
            aF[ks][mt][0] = sfq[(r + g) * SPADH + ks * 8 + t4];
            aF[ks][mt][1] = sfq[(r + g + 8) * SPADH + ks * 8 + t4];
            aF[ks][mt][2] = sfq[(r + g) * SPADH + ks * 8 + t4 + 4];
            aF[ks][mt][3] = sfq[(r + g + 8) * SPADH + ks * 8 + t4 + 4];
        }

    float s[4] = {0.f, 0.f, 0.f, 0.f}, tt[4] = {0.f, 0.f, 0.f, 0.f};

    for (int nc = 0; nc < 192; nc += 32) {
        float c[2][4][4];
        #pragma unroll
        for (int mt = 0; mt < 2; mt++)
            #pragma unroll
            for (int nt = 0; nt < 4; nt++)
                #pragma unroll
                for (int r = 0; r < 4; r++) c[mt][nt][r] = 0.f;

        #pragma unroll
        for (int ks = 0; ks < 2; ks++)
            #pragma unroll
            for (int nt = 0; nt < 4; nt++) {
                const uint32_t b0 = sfk[(nc + nt * 8 + g) * SPADH + ks * 8 + t4];
                const uint32_t b1 = sfk[(nc + nt * 8 + g) * SPADH + ks * 8 + t4 + 4];
                mma_bf16(c[0][nt], aF[ks][0], b0, b1);
                mma_bf16(c[1][nt], aF[ks][1], b0, b1);
            }

        #pragma unroll
        for (int nt = 0; nt < 4; nt++) {
            const int col0 = nc + nt * 8 + 2 * t4;
            const float2 bv0 = sbv[col0];
            const float2 bv1 = sbv[col0 + 1];
            #pragma unroll
            for (int mt = 0; mt < 2; mt++) {
                const float e0 = __expf(c[mt][nt][0] + bv0.x);
                const float e1 = __expf(c[mt][nt][1] + bv1.x);
                const float e2 = __expf(c[mt][nt][2] + bv0.x);
                const float e3 = __expf(c[mt][nt][3] + bv1.x);
                s[mt * 2 + 0] += e0 + e1;
                tt[mt * 2 + 0] += e0 * bv0.y + e1 * bv1.y;
                s[mt * 2 + 1] += e2 + e3;
                tt[mt * 2 + 1] += e2 * bv0.y + e3 * bv1.y;
            }
        }
    }

    #pragma unroll
    for (int i = 0; i < 4; i++) {
        s[i] += __shfl_xor_sync(0xffffffffu, s[i], 1);
        s[i] += __shfl_xor_sync(0xffffffffu, s[i], 2);
        tt[i] += __shfl_xor_sync(0xffffffffu, tt[i], 1);
        tt[i] += __shfl_xor_sync(0xffffffffu, tt[i], 2);
        sOut[i] = s[i]; tOut[i] = tt[i];
    }
    rows[0] = m0 + g;
    rows[1] = m0 + g + 8;
    rows[2] = m0 + 16 + g;
    rows[3] = m0 + 24 + g;
}

// ---------------- K23: both attention directions (z = dir), bf16 staged ----------------
__global__ __launch_bounds__(192) void k23_attn(const float* __restrict__ mask)
{
    extern __shared__ uint32_t smem[];
    uint32_t* sfq = smem;                                    // 192*SPADH
    uint32_t* sfk = sfq + 192 * SPADH;
    float2* sbv = reinterpret_cast<float2*>(sfk + 192 * SPADH);

    const int b = blockIdx.x, y = blockIdx.y, dir = blockIdx.z;
    const int tid = threadIdx.x;

    if (dir == 0) {
        const int base = (b * KPn + y) * KQn;
        const uint4* fq4 = reinterpret_cast<const uint4*>(g_fq + base * 16);
        const uint4* fk4 = reinterpret_cast<const uint4*>(g_fk + base * 16);
        for (int i = tid; i < 192 * 4; i += 192) {
            const int row = i >> 2, f4 = i & 3;
            uint4 v = fq4[i];
            uint32_t* dq = sfq + row * SPADH + f4 * 4;
            dq[0] = v.x; dq[1] = v.y; dq[2] = v.z; dq[3] = v.w;
            uint4 w = fk4[i];
            uint32_t* dk = sfk + row * SPADH + f4 * 4;
            dk[0] = w.x; dk[1] = w.y; dk[2] = w.z; dk[3] = w.w;
        }
        sbv[tid] = make_float2((mask[base + tid] < 0.5f) ? NEGV : 0.f, g_vw[base + tid]);
        __syncthreads();

        float s[4], t[4]; int rows[4];
        attn_mma_core(sfq, sfk, sbv, tid, s, t, rows);
        if ((tid & 3) == 0) {
            #pragma unroll
            for (int i = 0; i < 4; i++) g_Umh[base + rows[i]] = t[i] / s[i];
        }
    } else {
        const int q = y;
        const uint4* fqg = reinterpret_cast<const uint4*>(g_fq);
        const uint4* fkg = reinterpret_cast<const uint4*>(g_fk);
        for (int i = tid; i < 192 * 4; i += 192) {
            const int row = i >> 2, f4 = i & 3;
            const int gidx = ((b * KPn + row) * KQn + q) * 4 + f4;
            uint4 v = fqg[gidx];
            uint32_t* dq = sfq + row * SPADH + f4 * 4;
            dq[0] = v.x; dq[1] = v.y; dq[2] = v.z; dq[3] = v.w;
            uint4 w = fkg[gidx];
            uint32_t* dk = sfk + row * SPADH + f4 * 4;
            dk[0] = w.x; dk[1] = w.y; dk[2] = w.z; dk[3] = w.w;
        }
        {
            const int idx = (b * KPn + tid) * KQn + q;
            sbv[tid] = make_float2((mask[idx] < 0.5f) ? NEGV : 0.f, g_vw[idx]);
        }
        __syncthreads();

        float s[4], t[4]; int rows[4];
        attn_mma_core(sfq, sfk, sbv, tid, s, t, rows);
        if ((tid & 3) == 0) {
            #pragma unroll
            for (int i = 0; i < 4; i++)
                g_Umv[(b * KPn + rows[i]) * KQn + q] = t[i] / s[i];
        }
    }
}

// ---------------- K4: U via tf32 MMA, 64x32 tiles (72 blocks) ----------------
__global__ __launch_bounds__(256) void k4_U(
    const float* __restrict__ Eq, const float* __restrict__ Ep,
    const float* __restrict__ W_out, const float* __restrict__ mask)
{
    __shared__ uint32_t sA[64 * 36];
    __shared__ uint32_t sB[32 * 36];
    __shared__ float sw3[Hn];

    const int b = blockIdx.z;
    const int row0 = blockIdx.y * 64;   // p
    const int col0 = blockIdx.x * 32;   // q
    const int tid = threadIdx.x;
    const int wid = tid >> 5, lane = tid & 31, g = lane >> 2, t4 = lane & 3;
    const int wr = wid & 1, wc = wid >> 1;
    float c[2][4] = {};

    for (int i = tid; i < Hn; i += 256) sw3[i] = W_out[2 * Hn + i];
    __syncthreads();

    for (int kc = 0; kc < Hn; kc += 32) {
        #pragma unroll
        for (int h = 0; h < 2; h++) {
            const int i = tid + h * 256;
            const int r = i >> 3, j4 = i & 7;
            float4 av = *reinterpret_cast<const float4*>(Ep + (b * KPn + row0 + r) * Hn + kc + j4 * 4);
            uint32_t* da = sA + r * 36 + j4 * 4;
            da[0] = tf32cvt(av.x); da[1] = tf32cvt(av.y); da[2] = tf32cvt(av.z); da[3] = tf32cvt(av.w);
        }
        {
            const int r = tid >> 3, j4 = tid & 7;
            float4 bv = *reinterpret_cast<const float4*>(Eq + (b * KQn + col0 + r) * Hn + kc + j4 * 4);
            uint32_t* db = sB + r * 36 + j4 * 4;
            db[0] = tf32cvt(bv.x * sw3[kc + j4 * 4 + 0]);
            db[1] = tf32cvt(bv.y * sw3[kc + j4 * 4 + 1]);
            db[2] = tf32cvt(bv.z * sw3[kc + j4 * 4 + 2]);
            db[3] = tf32cvt(bv.w * sw3[kc + j4 * 4 + 3]);
        }
        __syncthreads();
        #pragma unroll
        for (int ks = 0; ks < 4; ks++) {
            uint32_t a[2][4];
            #pragma unroll
            for (int mt = 0; mt < 2; mt++) {
                const int r = wr * 32 + mt * 16;
                a[mt][0] = sA[(r + g) * 36 + ks * 8 + t4];
                a[mt][1] = sA[(r + g + 8) * 36 + ks * 8 + t4];
                a[mt][2] = sA[(r + g) * 36 + ks * 8 + t4 + 4];
                a[mt][3] = sA[(r + g + 8) * 36 + ks * 8 + t4 + 4];
            }
            const uint32_t b0 = sB[(wc * 8 + g) * 36 + ks * 8 + t4];
            const uint32_t b1 = sB[(wc * 8 + g) * 36 + ks * 8 + t4 + 4];
            mma_tf32(c[0], a[0], b0, b1);
            mma_tf32(c[1], a[1], b0, b1);
        }
        __syncthreads();
    }

    #pragma unroll
    for (int mt = 0; mt < 2; mt++)
        #pragma unroll
        for (int half = 0; half < 2; half++) {
            const int row = row0 + wr * 32 + mt * 16 + g + half * 8;
            const int col = col0 + wc * 8 + 2 * t4;
            const int idx = (b * KPn + row) * KQn + col;
            const float u2v = g_u2[b * KPn + row];
            float U0 = c[mt][half * 2 + 0] + g_u1[b * KQn + col] + u2v + g_Umh[idx] + g_Umv[idx];
            float U1 = c[mt][half * 2 + 1] + g_u1[b * KQn + col + 1] + u2v + g_Umh[idx + 1] + g_Umv[idx + 1];
            if (mask[idx] < 0.5f) U0 = NEGV;
            if (mask[idx + 1] < 0.5f) U1 = NEGV;
            *reinterpret_cast<float2*>(g_U + idx) = make_float2(U0, U1);
        }
}

// ---------------- K5: both softmax aggregations (z = dir), merged ----------------
__global__ __launch_bounds__(256) void k5_soft(const float* __restrict__ Eq, const float* __restrict__ Ep)
{
    const int b = blockIdx.x, y = blockIdx.y, dir = blockIdx.z;
    __shared__ float sw[192];
    __shared__ float red[256];
    const int tid = threadIdx.x;

    float v;
    if (dir == 0) v = (tid < KQn) ? g_U[(b * KPn + y) * KQn + tid] : -3.4e38f;
    else          v = (tid < KPn) ? g_U[(b * KPn + tid) * KQn + y] : -3.4e38f;
    red[tid] = v; __syncthreads();
    for (int o = 128; o; o >>= 1) { if (tid < o) red[tid] = fmaxf(red[tid], red[tid + o]); __syncthreads(); }
    const float m = red[0]; __syncthreads();
    const float e = (tid < 192) ? __expf(v - m) : 0.f;
    red[tid] = e; __syncthreads();
    for (int o = 128; o; o >>= 1) { if (tid < o) red[tid] += red[tid + o]; __syncthreads(); }
    const float inv = 1.f / red[0];
    if (tid < 192) sw[tid] = e * inv;
    __syncthreads();

    const int h = tid;
    float a0 = 0.f, a1 = 0.f;
    if (dir == 0) {
        for (int k = 0; k < KQn; k += 2) {
            a0 += sw[k] * Eq[(b * KQn + k) * Hn + h];
            a1 += sw[k + 1] * Eq[(b * KQn + k + 1) * Hn + h];
        }
        const float a = a0 + a1;
        const float ep = Ep[(b * KPn + y) * Hn + h];
        float* G = g_Gl + (b * KPn + y) * Rn;
        G[h] = ep; G[Hn + h] = a; G[2 * Hn + h] = ep * a;
    } else {
        for (int k = 0; k < KPn; k += 2) {
            a0 += sw[k] * Ep[(b * KPn + k) * Hn + h];
            a1 += sw[k + 1] * Ep[(b * KPn + k + 1) * Hn + h];
        }
        const float a = a0 + a1;
        const float eq = Eq[(b * KQn + y) * Hn + h];
        float* G = g_Gr + (b * KQn + y) * Rn;
        G[h] = eq; G[Hn + h] = a; G[2 * Hn + h] = eq * a;
    }
}

// ---------------- K6: gates via tf32 MMA, 64x64 tile ----------------
__global__ __launch_bounds__(256) void k6_gate(
    const float* __restrict__ Wl, const float* __restrict__ bl,
    const float* __restrict__ Wr, const float* __restrict__ br)
{
    __shared__ uint32_t sG[64 * 36];
    __shared__ uint32_t sW[64 * 36];

    const int side = blockIdx.z;
    const float* __restrict__ G = side ? g_Gr : g_Gl;
    const float* __restrict__ W = side ? Wr : Wl;
    const float* __restrict__ bias = side ? br : bl;
    float* __restrict__ outp = side ? g_right : g_left;
    const int row0 = blockIdx.y * 64;
    const int col0 = blockIdx.x * 64;

    const int tid = threadIdx.x;
    const int wid = tid >> 5, lane = tid & 31, g = lane >> 2, t4 = lane & 3;
    const int wr = wid >> 2, wc = wid & 3;
    float c[2][2][4] = {};

    for (int kc = 0; kc < Rn; kc += 32) {
        #pragma unroll
        for (int h = 0; h < 2; h++) {
            const int i = tid + h * 256;
            const int r = i >> 3, j4 = i & 7;
            float4 gv = *reinterpret_cast<const float4*>(G + (row0 + r) * Rn + kc + j4 * 4);
            uint32_t* dg = sG + r * 36 + j4 * 4;
            dg[0] = tf32cvt(gv.x); dg[1] = tf32cvt(gv.y); dg[2] = tf32cvt(gv.z); dg[3] = tf32cvt(gv.w);
            float4 wv = *reinterpret_cast<const float4*>(W + (col0 + r) * Rn + kc + j4 * 4);
            uint32_t* dw = sW + r * 36 + j4 * 4;
            dw[0] = tf32cvt(wv.x); dw[1] = tf32cvt(wv.y); dw[2] = tf32cvt(wv.z); dw[3] = tf32cvt(wv.w);
        }
        __syncthreads();
        #pragma unroll
        for (int ks = 0; ks < 4; ks++) {
            uint32_t a[2][4];
            #pragma unroll
            for (int mt = 0; mt < 2; mt++) {
                const int r = wr * 32 + mt * 16;
                a[mt][0] = sG[(r + g) * 36 + ks * 8 + t4];
                a[mt][1] = sG[(r + g + 8) * 36 + ks * 8 + t4];
                a[mt][2] = sG[(r + g) * 36 + ks * 8 + t4 + 4];
                a[mt][3] = sG[(r + g + 8) * 36 + ks * 8 + t4 + 4];
            }
            #pragma unroll
            for (int nt = 0; nt < 2; nt++) {
                const uint32_t b0 = sW[(wc * 16 + nt * 8 + g) * 36 + ks * 8 + t4];
                const uint32_t b1 = sW[(wc * 16 + nt * 8 + g) * 36 + ks * 8 + t4 + 4];
                mma_tf32(c[0][nt], a[0], b0, b1);
                mma_tf32(c[1][nt], a[1], b0, b1);
            }
        }
        __syncthreads();
    }

    #pragma unroll
    for (int mt = 0; mt < 2; mt++)
        #pragma unroll
        for (int nt = 0; nt < 2; nt++) {
            const int row = row0 + wr * 32 + mt * 16 + g;
            const int col = col0 + wc * 16 + nt * 8 + 2 * t4;
            const float b0f = bias[col], b1f = bias[col + 1];
            {
                float2 gv = *reinterpret_cast<const float2*>(G + row * Rn + col);
                const float s0 = 1.f / (1.f + __expf(-(c[mt][nt][0] + b0f)));
                const float s1 = 1.f / (1.f + __expf(-(c[mt][nt][1] + b1f)));
                *reinterpret_cast<float2*>(outp + row * Rn + col) = make_float2(s0 * gv.x, s1 * gv.y);
            }
            {
                float2 gv = *reinterpret_cast<const float2*>(G + (row + 8) * Rn + col);
                const float s2 = 1.f / (1.f + __expf(-(c[mt][nt][2] + b0f)));
                const float s3 = 1.f / (1.f + __expf(-(c[mt][nt][3] + b1f)));
                *reinterpret_cast<float2*>(outp + (row + 8) * Rn + col) = make_float2(s2 * gv.x, s3 * gv.y);
            }
        }
}

// ---------------- K7: split-K partials via 3-term split-tf32 MMA ----------------
__global__ __launch_bounds__(256) void k7_partial()
{
    __shared__ uint32_t hA[64 * 36], lA[64 * 36], hB[64 * 36], lB[64 * 36];

    const int z = blockIdx.z;
    const int b = z >> 2, ksz = z & 3;
    const int kbase = ksz * 192;
    const float* __restrict__ A = g_left + b * KPn * Rn;
    const float* __restrict__ Bm = g_right + b * KQn * Rn;
    const int row0 = blockIdx.y * 64;
    const int col0 = blockIdx.x * 64;
    const int tid = threadIdx.x;
    const int wid = tid >> 5, lane = tid & 31, g = lane >> 2, t4 = lane & 3;
    const int wr = wid >> 2, wc = wid & 3;
    float c[2][2][4] = {};

    for (int kc = kbase; kc < kbase + 192; kc += 32) {
        #pragma unroll
        for (int h = 0; h < 2; h++) {
            const int i = tid + h * 256;
            const int r = i >> 3, j4 = i & 7;
            float4 av = *reinterpret_cast<const float4*>(A + (row0 + r) * Rn + kc + j4 * 4);
            float4 bv = *reinterpret_cast<const float4*>(Bm + (col0 + r) * Rn + kc + j4 * 4);
            #pragma unroll
            for (int e = 0; e < 4; e++) {
                const float xa = (&av.x)[e];
                const uint32_t ha = tf32cvt(xa);
                hA[r * 36 + j4 * 4 + e] = ha;
                lA[r * 36 + j4 * 4 + e] = tf32cvt(xa - __uint_as_float(ha));
                const float xb = (&bv.x)[e];
                const uint32_t hb = tf32cvt(xb);
                hB[r * 36 + j4 * 4 + e] = hb;
                lB[r * 36 + j4 * 4 + e] = tf32cvt(xb - __uint_as_float(hb));
            }
        }
        __syncthreads();
        #pragma unroll
        for (int ks = 0; ks < 4; ks++) {
            uint32_t aH[2][4], aL[2][4];
            #pragma unroll
            for (int mt = 0; mt < 2; mt++) {
                const int r = wr * 32 + mt * 16;
                aH[mt][0] = hA[(r + g) * 36 + ks * 8 + t4];
                aH[mt][1] = hA[(r + g + 8) * 36 + ks * 8 + t4];
                aH[mt][2] = hA[(r + g) * 36 + ks * 8 + t4 + 4];
                aH[mt][3] = hA[(r + g + 8) * 36 + ks * 8 + t4 + 4];
                aL[mt][0] = lA[(r + g) * 36 + ks * 8 + t4];
                aL[mt][1] = lA[(r + g + 8) * 36 + ks * 8 + t4];
                aL[mt][2] = lA[(r + g) * 36 + ks * 8 + t4 + 4];
                aL[mt][3] = lA[(r + g + 8) * 36 + ks * 8 + t4 + 4];
            }
            #pragma unroll
            for (int nt = 0; nt < 2; nt++) {
                const int rb = wc * 16 + nt * 8 + g;
                const uint32_t bh0 = hB[rb * 36 + ks * 8 + t4];
                const uint32_t bh1 = hB[rb * 36 + ks * 8 + t4 + 4];
                const uint32_t bl0 = lB[rb * 36 + ks * 8 + t4];
                const uint32_t bl1 = lB[rb * 36 + ks * 8 + t4 + 4];
                #pragma unroll
                for (int mt = 0; mt < 2; mt++) {
                    mma_tf32(c[mt][nt], aH[mt], bh0, bh1);
                    mma_tf32(c[mt][nt], aH[mt], bl0, bl1);
                    mma_tf32(c[mt][nt], aL[mt], bh0, bh1);
                }
            }
        }
        __syncthreads();
    }

    float* dst = g_part + ksz * (BB * KPn * KQn) + b * (KPn * KQn);
    #pragma unroll
    for (int mt = 0; mt < 2; mt++)
        #pragma unroll
        for (int nt = 0; nt < 2; nt++)
            #pragma unroll
            for (int half = 0; half < 2; half++) {
                const int row = row0 + wr * 32 + mt * 16 + g + half * 8;
                const int col = col0 + wc * 16 + nt * 8 + 2 * t4;
                *reinterpret_cast<float2*>(dst + row * KQn + col) =
                    make_float2(c[mt][nt][half * 2 + 0], c[mt][nt][half * 2 + 1]);
            }
}

// ---------------- K8: reduce split-K + relu ----------------
__global__ __launch_bounds__(256) void k8_reduce(float* __restrict__ outp)
{
    const int idx = blockIdx.x * 256 + threadIdx.x;
    const int n = BB * KPn * KQn;
    if (idx < n) {
        float s = (g_part[idx] + g_part[n + idx]) + (g_part[2 * n + idx] + g_part[3 * n + idx]);
        outp[idx] = fmaxf(s, 0.f);
    }
}

// ---------------- launch ----------------
extern "C" void kernel_launch(void* const* d_in, const int* in_sizes, int n_in,
                              void* d_out, int out_size)
{
    const float* Eq    = (const float*)d_in[0];
    const float* Ep    = (const float*)d_in[1];
    const float* mask  = (const float*)d_in[2];
    const float* W_in  = (const float*)d_in[3];
    const float* Wq    = (const float*)d_in[4];
    const float* bq    = (const float*)d_in[5];
    const float* Wk    = (const float*)d_in[6];
    const float* bk    = (const float*)d_in[7];
    const float* Wv    = (const float*)d_in[8];
    const float* bv    = (const float*)d_in[9];
    const float* Wo1   = (const float*)d_in[10];
    const float* bo1   = (const float*)d_in[11];
    const float* Wo2   = (const float*)d_in[12];
    const float* bo2   = (const float*)d_in[13];
    const float* W_out = (const float*)d_in[14];
    const float* Wl    = (const float*)d_in[15];
    const float* bl    = (const float*)d_in[16];
    const float* Wr    = (const float*)d_in[17];
    const float* br    = (const float*)d_in[18];
    float* outp = (float*)d_out;

    const int smemAttn = 2 * 192 * SPADH * 4 + 192 * 8;                // 29184 B
    const int smemK1 = (32 * 260 + 192 * 36) * 4 + (Hn + Tn) * 4;      // 62080 B
    cudaFuncSetAttribute(k23_attn, cudaFuncAttributeMaxDynamicSharedMemorySize, smemAttn);
    cudaFuncSetAttribute(k1_pair, cudaFuncAttributeMaxDynamicSharedMemorySize, smemK1);

    k0_rowproj<<<dim3(BB, 2, 4), dim3(32, 8)>>>(Eq, Ep, W_in, W_out);
    k0b_wv4<<<1, 32>>>(Wv, bv, W_out);
    k1_pair<<<dim3(BB, KPn), 192, smemK1>>>(Eq, Ep, W_in, Wq, bq, Wk, bk, Wo1, bo1, Wo2, bo2);
    k23_attn<<<dim3(BB, 192, 2), 192, smemAttn>>>(mask);
    k4_U<<<dim3(6, 3, BB), 256>>>(Eq, Ep, W_out, mask);
    k5_soft<<<dim3(BB, 192, 2), 256>>>(Eq, Ep);
    k6_gate<<<dim3(12, 12, 2), 256>>>(Wl, bl, Wr, br);
    k7_partial<<<dim3(3, 3, 16), 256>>>();
    k8_reduce<<<dim3(576), 256>>>(outp);
}

// round 16
// speedup vs baseline: 1.1920x; 1.0954x over previous
#include <cuda_runtime.h>
#include <cuda_bf16.h>
#include <math.h>
#include <stdint.h>

#define BB 4
#define KQn 192
#define KPn 192
#define Hn 256
#define Tn 32
#define Rn 768
#define NEGV (-1e9f)
#define SCALEV (0.17677669529663687f)   // 1/sqrt(32)
#define SPADH 18                         // bf16 smem row stride in u32 words

// ---------------- scratch ----------------
static __device__ float g_A1[BB * KQn * Tn];
static __device__ float g_A2[BB * KPn * Tn];
static __device__ float g_u1[BB * KQn];
static __device__ float g_u2[BB * KPn];
static __device__ uint32_t g_fq[BB * KPn * KQn * 16];  // bf16x2 packed
static __device__ uint32_t g_fk[BB * KPn * KQn * 16];  // bf16x2 packed, pre-scaled by obv*SCALE
static __device__ float g_vw[BB * KPn * KQn];
static __device__ float g_wv4[Tn];
static __device__ float g_c0[1];
static __device__ float g_Umh[BB * KPn * KQn];
static __device__ float g_Umv[BB * KPn * KQn];
static __device__ float g_U[BB * KPn * KQn];
static __device__ float g_Gl[BB * KPn * Rn];
static __device__ float g_Gr[BB * KQn * Rn];
static __device__ float g_left[BB * KPn * Rn];
static __device__ float g_right[BB * KQn * Rn];
static __device__ float g_part[4 * BB * KPn * KQn];

__device__ __forceinline__ uint32_t tf32cvt(float x) {
    uint32_t u;
    asm("cvt.rna.tf32.f32 %0, %1;" : "=r"(u) : "f"(x));
    return u;
}

__device__ __forceinline__ uint32_t packbf(float lo, float hi) {
    __nv_bfloat162 h = __floats2bfloat162_rn(lo, hi);
    return *reinterpret_cast<uint32_t*>(&h);
}

__device__ __forceinline__ void mma_tf32(float c[4], const uint32_t a[4], uint32_t b0, uint32_t b1) {
    asm volatile("mma.sync.aligned.m16n8k8.row.col.f32.tf32.tf32.f32 "
        "{%0,%1,%2,%3}, {%4,%5,%6,%7}, {%8,%9}, {%0,%1,%2,%3};"
        : "+f"(c[0]), "+f"(c[1]), "+f"(c[2]), "+f"(c[3])
        : "r"(a[0]), "r"(a[1]), "r"(a[2]), "r"(a[3]), "r"(b0), "r"(b1));
}

__device__ __forceinline__ void mma_bf16(float c[4], const uint32_t a[4], uint32_t b0, uint32_t b1) {
    asm volatile("mma.sync.aligned.m16n8k16.row.col.f32.bf16.bf16.f32 "
        "{%0,%1,%2,%3}, {%4,%5,%6,%7}, {%8,%9}, {%0,%1,%2,%3};"
        : "+f"(c[0]), "+f"(c[1]), "+f"(c[2]), "+f"(c[3])
        : "r"(a[0]), "r"(a[1]), "r"(a[2]), "r"(a[3]), "r"(b0), "r"(b1));
}

// ---------------- K0: per-row projections A1/A2 and u1/u2 ----------------
__global__ __launch_bounds__(256) void k0_rowproj(
    const float* __restrict__ Eq, const float* __restrict__ Ep,
    const float* __restrict__ W_in, const float* __restrict__ W_out)
{
    const int b = blockIdx.x;
    const int side = blockIdx.y;
    const float* src = side ? (Ep + b * KPn * Hn) : (Eq + b * KQn * Hn);
    const int woff = side ? Hn : 0;
    float* A = side ? (g_A2 + b * KPn * Tn) : (g_A1 + b * KQn * Tn);
    float* u = side ? (g_u2 + b * KPn) : (g_u1 + b * KQn);

    __shared__ float sW[Tn][Hn + 1];
    __shared__ float swv[Hn];
    const int tid = threadIdx.y * 32 + threadIdx.x;
    for (int i = tid; i < Tn * Hn; i += 256) {
        int t = i >> 8, h = i & 255;
        sW[t][h] = W_in[t * Rn + woff + h];
    }
    for (int i = tid; i < Hn; i += 256) swv[i] = W_out[woff + i];
    __syncthreads();

    const int t = threadIdx.x;
    const int y0 = blockIdx.z * 48;
    for (int y = y0 + threadIdx.y; y < y0 + 48; y += 8) {
        const float* row = src + y * Hn;
        float p0 = 0.f, p1 = 0.f, p2 = 0.f, p3 = 0.f, up = 0.f;
        for (int h = 0; h < Hn; h += 4) {
            p0 += row[h] * sW[t][h];
            p1 += row[h + 1] * sW[t][h + 1];
            p2 += row[h + 2] * sW[t][h + 2];
            p3 += row[h + 3] * sW[t][h + 3];
        }
        for (int h = t; h < Hn; h += 32) up += row[h] * swv[h];
        #pragma unroll
        for (int o = 16; o; o >>= 1) up += __shfl_down_sync(0xffffffffu, up, o);
        A[y * Tn + t] = (p0 + p1) + (p2 + p3);
        if (t == 0) u[y] = up;
    }
}

// ---------------- K0b: wv4 = Wv^T @ w4, c0 = bv . w4 ----------------
__global__ void k0b_wv4(const float* __restrict__ Wv, const float* __restrict__ bv,
                        const float* __restrict__ W_out)
{
    const int t = threadIdx.x;
    float s = 0.f;
    for (int u = 0; u < Tn; u++) s += Wv[u * Tn + t] * W_out[Rn + u];
    g_wv4[t] = s;
    float c = bv[t] * W_out[Rn + t];
    #pragma unroll
    for (int o = 16; o; o >>= 1) c += __shfl_down_sync(0xffffffffu, c, o);
    if (t == 0) g_c0[0] = c;
}

// ---------------- K1: bf16 bilinear MMA -> E1 -> bf16 projection MMA ----------------
__global__ __launch_bounds__(192) void k1_pair(
    const float* __restrict__ Eq, const float* __restrict__ Ep,
    const float* __restrict__ W_in,
    const float* __restrict__ Wq, const float* __restrict__ bq,
    const float* __restrict__ Wk, const float* __restrict__ bk,
    const float* __restrict__ Wo1, const float* __restrict__ bo1,
    const float* __restrict__ Wo2, const float* __restrict__ bo2)
{
    __shared__ uint32_t sWbuf[32 * 130];   // W3 bf16 (stride 130); reused as Wcat (stride 18)
    __shared__ uint32_t sA[192 * SPADH];   // A chunks bf16, then E1 bf16
    __shared__ float sEpRow[Hn];
    __shared__ float sA2[Tn];

    const int b = blockIdx.x, p = blockIdx.y;
    const int tid = threadIdx.x;
    const int wid = tid >> 5, lane = tid & 31, g = lane >> 2, t4 = lane & 3;
    const int m0 = wid * 32;

    // stage W3 bf16 (stride 130 words)
    for (int i = tid; i < 32 * 64; i += 192) {
        const int t = i >> 6, h4 = i & 63;
        float4 w = reinterpret_cast<const float4*>(W_in + t * Rn + 2 * Hn)[h4];
        sWbuf[t * 130 + h4 * 2]     = packbf(w.x, w.y);
        sWbuf[t * 130 + h4 * 2 + 1] = packbf(w.z, w.w);
    }
    for (int i = tid; i < Hn / 4; i += 192)
        reinterpret_cast<float4*>(sEpRow)[i] =
            reinterpret_cast<const float4*>(Ep + (b * KPn + p) * Hn)[i];
    if (tid < Tn) sA2[tid] = g_A2[(b * KPn + p) * Tn + tid];
    __syncthreads();

    // ---- stage 1: bilinear E1 = (Eq o Ep) @ W3^T, bf16 ----
    float c1[2][4][4] = {};
    const float4* eqrow = reinterpret_cast<const float4*>(Eq + (b * KQn + tid) * Hn);
    const float4* sEpRow4 = reinterpret_cast<const float4*>(sEpRow);

    for (int kc = 0; kc < 8; kc++) {
        #pragma unroll
        for (int j = 0; j < 8; j++) {
            float4 e = eqrow[kc * 8 + j];
            float4 pp = sEpRow4[kc * 8 + j];
            sA[tid * SPADH + j * 2]     = packbf(e.x * pp.x, e.y * pp.y);
            sA[tid * SPADH + j * 2 + 1] = packbf(e.z * pp.z, e.w * pp.w);
        }
        __syncwarp();
        #pragma unroll
        for (int ks = 0; ks < 2; ks++) {
            uint32_t a[2][4];
            #pragma unroll
            for (int mt = 0; mt < 2; mt++) {
                const int r = m0 + mt * 16;
                a[mt][0] = sA[(r + g) * SPADH + ks * 8 + t4];
                a[mt][1] = sA[(r + g + 8) * SPADH + ks * 8 + t4];
                a[mt][2] = sA[(r + g) * SPADH + ks * 8 + t4 + 4];
                a[mt][3] = sA[(r + g + 8) * SPADH + ks * 8 + t4 + 4];
            }
            #pragma unroll
            for (int nt = 0; nt < 4; nt++) {
                const uint32_t b0 = sWbuf[(nt * 8 + g) * 130 + kc * 16 + ks * 8 + t4];
                const uint32_t b1 = sWbuf[(nt * 8 + g) * 130 + kc * 16 + ks * 8 + t4 + 4];
                mma_bf16(c1[0][nt], a[0], b0, b1);
                mma_bf16(c1[1][nt], a[1], b0, b1);
            }
        }
        __syncwarp();
    }

    // finalize E1 (add A1 + A2) in fragment owners; pack bf16 into sA (warp-local rows)
    #pragma unroll
    for (int mt = 0; mt < 2; mt++)
        #pragma unroll
        for (int nt = 0; nt < 4; nt++) {
            const int r0 = m0 + mt * 16 + g;
            const int col = nt * 8 + 2 * t4;
            const int w = nt * 4 + t4;
            float2 a1a = *reinterpret_cast<const float2*>(g_A1 + (b * KQn + r0) * Tn + col);
            float2 a1b = *reinterpret_cast<const float2*>(g_A1 + (b * KQn + r0 + 8) * Tn + col);
            const float s2a = sA2[col], s2b = sA2[col + 1];
            sA[r0 * SPADH + w] = packbf(c1[mt][nt][0] + a1a.x + s2a,
                                        c1[mt][nt][1] + a1a.y + s2b);
            sA[(r0 + 8) * SPADH + w] = packbf(c1[mt][nt][2] + a1b.x + s2a,
                                              c1[mt][nt][3] + a1b.y + s2b);
        }
    __syncthreads();   // all warps done with sWbuf stage-1 reads

    // Wcat bf16 (stride 18): rows 0-31 Wo1, 32-63 Wq, 64-95 Wk, 96 wv4, 97-103 zero
    for (int i = tid; i < 104 * 16; i += 192) {
        const int n = i >> 4, wslot = i & 15;
        const int t0 = wslot * 2;
        float w0v = 0.f, w1v = 0.f;
        if (n < 32)       { w0v = Wo1[n * 32 + t0]; w1v = Wo1[n * 32 + t0 + 1]; }
        else if (n < 64)  { w0v = Wq[(n - 32) * 32 + t0]; w1v = Wq[(n - 32) * 32 + t0 + 1]; }
        else if (n < 96)  { w0v = Wk[(n - 64) * 32 + t0]; w1v = Wk[(n - 64) * 32 + t0 + 1]; }
        else if (n == 96) { w0v = g_wv4[t0]; w1v = g_wv4[t0 + 1]; }
        sWbuf[n * SPADH + wslot] = packbf(w0v, w1v);
    }
    __syncthreads();

    const int pairbase = (b * KPn + p) * KQn;
    const float bo2v = bo2[0];
    const float c0v = g_c0[0];
    float scReg[4];

    // E1 fragments (shared by all three projection groups)
    uint32_t aF[2][2][4];
    #pragma unroll
    for (int ks = 0; ks < 2; ks++)
        #pragma unroll
        for (int mt = 0; mt < 2; mt++) {
            const int r = m0 + mt * 16;
            aF[ks][mt][0] = sA[(r + g) * SPADH + ks * 8 + t4];
            aF[ks][mt][1] = sA[(r + g + 8) * SPADH + ks * 8 + t4];
            aF[ks][mt][2] = sA[(r + g) * SPADH + ks * 8 + t4 + 4];
            aF[ks][mt][3] = sA[(r + g + 8) * SPADH + ks * 8 + t4 + 4];
        }

    // G0: Wo1 -> sc
    {
        float c[2][4][4] = {};
        #pragma unroll
        for (int ks = 0; ks < 2; ks++)
            #pragma unroll
            for (int nt = 0; nt < 4; nt++) {
                const uint32_t b0 = sWbuf[(nt * 8 + g) * SPADH + ks * 8 + t4];
                const uint32_t b1 = sWbuf[(nt * 8 + g) * SPADH + ks * 8 + t4 + 4];
                mma_bf16(c[0][nt], aF[ks][0], b0, b1);
                mma_bf16(c[1][nt], aF[ks][1], b0, b1);
            }
        #pragma unroll
        for (int mt = 0; mt < 2; mt++)
            #pragma unroll
            for (int half = 0; half < 2; half++) {
                float part = 0.f;
                #pragma unroll
                for (int nt = 0; nt < 4; nt++) {
                    const int col = nt * 8 + 2 * t4;
                    part += fmaxf(c[mt][nt][half * 2 + 0] + bo1[col], 0.f) * Wo2[col]
                          + fmaxf(c[mt][nt][half * 2 + 1] + bo1[col + 1], 0.f) * Wo2[col + 1];
                }
                part += __shfl_xor_sync(0xffffffffu, part, 1);
                part += __shfl_xor_sync(0xffffffffu, part, 2);
                scReg[mt * 2 + half] = SCALEV / (1.f + __expf(-(part + bo2v)));
            }
    }

    // G1: Wq -> g_fq (bf16 packed)
    {
        float c[2][4][4] = {};
        #pragma unroll
        for (int ks = 0; ks < 2; ks++)
            #pragma unroll
            for (int nt = 0; nt < 4; nt++) {
                const uint32_t b0 = sWbuf[(32 + nt * 8 + g) * SPADH + ks * 8 + t4];
                const uint32_t b1 = sWbuf[(32 + nt * 8 + g) * SPADH + ks * 8 + t4 + 4];
                mma_bf16(c[0][nt], aF[ks][0], b0, b1);
                mma_bf16(c[1][nt], aF[ks][1], b0, b1);
            }
        #pragma unroll
        for (int mt = 0; mt < 2; mt++)
            #pragma unroll
            for (int nt = 0; nt < 4; nt++) {
                const int r0 = m0 + mt * 16 + g;
                const int w = nt * 4 + t4;
                const int col = nt * 8 + 2 * t4;
                const float b0f = bq[col], b1f = bq[col + 1];
                g_fq[(pairbase + r0) * 16 + w]     = packbf(c[mt][nt][0] + b0f, c[mt][nt][1] + b1f);
                g_fq[(pairbase + r0 + 8) * 16 + w] = packbf(c[mt][nt][2] + b0f, c[mt][nt][3] + b1f);
            }
    }

    // G2: Wk + wv4 -> g_fk (bf16 packed, scaled) + g_vw
    {
        float c[2][5][4] = {};
        #pragma unroll
        for (int ks = 0; ks < 2; ks++)
            #pragma unroll
            for (int nt = 0; nt < 5; nt++) {
                const uint32_t b0 = sWbuf[(64 + nt * 8 + g) * SPADH + ks * 8 + t4];
                const uint32_t b1 = sWbuf[(64 + nt * 8 + g) * SPADH + ks * 8 + t4 + 4];
                mma_bf16(c[0][nt], aF[ks][0], b0, b1);
                mma_bf16(c[1][nt], aF[ks][1], b0, b1);
            }
        #pragma unroll
        for (int mt = 0; mt < 2; mt++)
            #pragma unroll
            for (int nt = 0; nt < 4; nt++) {
                const int r0 = m0 + mt * 16 + g;
                const int w = nt * 4 + t4;
                const int col = nt * 8 + 2 * t4;
                const float b0f = bk[col], b1f = bk[col + 1];
                const float s0 = scReg[mt * 2 + 0], s1 = scReg[mt * 2 + 1];
                g_fk[(pairbase + r0) * 16 + w]     = packbf((c[mt][nt][0] + b0f) * s0, (c[mt][nt][1] + b1f) * s0);
                g_fk[(pairbase + r0 + 8) * 16 + w] = packbf((c[mt][nt][2] + b0f) * s1, (c[mt][nt][3] + b1f) * s1);
            }
        if (t4 == 0) {
            #pragma unroll
            for (int mt = 0; mt < 2; mt++) {
                const int r0 = m0 + mt * 16 + g;
                g_vw[pairbase + r0] = c[mt][4][0] + c0v;
                g_vw[pairbase + r0 + 8] = c[mt][4][2] + c0v;
            }
        }
    }
}

// ================= bf16 tensor-core attention core =================
__device__ __forceinline__ void attn_mma_core(
    const uint32_t* __restrict__ sfq, const uint32_t* __restrict__ sfk,
    const float2* __restrict__ sbv, int tid, float sOut[4], float tOut[4], int rows[4])
{
    const int wid = tid >> 5, lane = tid & 31;
    const int g = lane >> 2, t4 = lane & 3;
    const int m0 = wid * 32;

    uint32_t aF[2][2][4];
    #pragma unroll
    for (int ks = 0; ks < 2; ks++)
        #pragma unroll
        for (int mt = 0; mt < 2; mt++) {
            const int r = m0 + mt * 16;
            aF[ks][mt][0] = sfq[(r + g) * SPADH + ks * 8 + t4];
            aF[ks][mt][1] = sfq[(r + g + 8) * SPADH + ks * 8 + t4];
            aF[ks][mt][2] = sfq[(r + g) * SPADH + ks * 8 + t4 + 4];
            aF[ks][mt][3] = sfq[(r + g + 8) * SPADH + ks * 8 + t4 + 4];
        }

    float s[4] = {0.f, 0.f, 0.f, 0.f}, tt[4] = {0.f, 0.f, 0.f, 0.f};

    for (int nc = 0; nc < 192; nc += 32) {
        float c[2][4][4];
        #pragma unroll
        for (int mt = 0; mt < 2; mt++)
            #pragma unroll
            for (int nt = 0; nt < 4; nt++)
                #pragma unroll
                for (int r = 0; r < 4; r++) c[mt][nt][r] = 0.f;

        #pragma unroll
        for (int ks = 0; ks < 2; ks++)
            #pragma unroll
            for (int nt = 0; nt < 4; nt++) {
                const uint32_t b0 = sfk[(nc + nt * 8 + g) * SPADH + ks * 8 + t4];
                const uint32_t b1 = sfk[(nc + nt * 8 + g) * SPADH + ks * 8 + t4 + 4];
                mma_bf16(c[0][nt], aF[ks][0], b0, b1);
                mma_bf16(c[1][nt], aF[ks][1], b0, b1);
            }

        #pragma unroll
        for (int nt = 0; nt < 4; nt++) {
            const int col0 = nc + nt * 8 + 2 * t4;
            const float2 bv0 = sbv[col0];
            const float2 bv1 = sbv[col0 + 1];
            #pragma unroll
            for (int mt = 0; mt < 2; mt++) {
                const float e0 = __expf(c[mt][nt][0] + bv0.x);
                const float e1 = __expf(c[mt][nt][1] + bv1.x);
                const float e2 = __expf(c[mt][nt][2] + bv0.x);
                const float e3 = __expf(c[mt][nt][3] + bv1.x);
                s[mt * 2 + 0] += e0 + e1;
                tt[mt * 2 + 0] += e0 * bv0.y + e1 * bv1.y;
                s[mt * 2 + 1] += e2 + e3;
                tt[mt * 2 + 1] += e2 * bv0.y + e3 * bv1.y;
            }
        }
    }

    #pragma unroll
    for (int i = 0; i < 4; i++) {
        s[i] += __shfl_xor_sync(0xffffffffu, s[i], 1);
        s[i] += __shfl_xor_sync(0xffffffffu, s[i], 2);
        tt[i] += __shfl_xor_sync(0xffffffffu, tt[i], 1);
        tt[i] += __shfl_xor_sync(0xffffffffu, tt[i], 2);
        sOut[i] = s[i]; tOut[i] = tt[i];
    }
    rows[0] = m0 + g;
    rows[1] = m0 + g + 8;
    rows[2] = m0 + 16 + g;
    rows[3] = m0 + 24 + g;
}

// ---------------- K23: both attention directions (z = dir), bf16 staged ----------------
__global__ __launch_bounds__(192) void k23_attn(const float* __restrict__ mask)
{
    extern __shared__ uint32_t smem[];
    uint32_t* sfq = smem;
    uint32_t* sfk = sfq + 192 * SPADH;
    float2* sbv = reinterpret_cast<float2*>(sfk + 192 * SPADH);

    const int b = blockIdx.x, y = blockIdx.y, dir = blockIdx.z;
    const int tid = threadIdx.x;

    if (dir == 0) {
        const int base = (b * KPn + y) * KQn;
        const uint4* fq4 = reinterpret_cast<const uint4*>(g_fq + base * 16);
        const uint4* fk4 = reinterpret_cast<const uint4*>(g_fk + base * 16);
        for (int i = tid; i < 192 * 4; i += 192) {
            const int row = i >> 2, f4 = i & 3;
            uint4 v = fq4[i];
            uint32_t* dq = sfq + row * SPADH + f4 * 4;
            dq[0] = v.x; dq[1] = v.y; dq[2] = v.z; dq[3] = v.w;
            uint4 w = fk4[i];
            uint32_t* dk = sfk + row * SPADH + f4 * 4;
            dk[0] = w.x; dk[1] = w.y; dk[2] = w.z; dk[3] = w.w;
        }
        sbv[tid] = make_float2((mask[base + tid] < 0.5f) ? NEGV : 0.f, g_vw[base + tid]);
        __syncthreads();

        float s[4], t[4]; int rows[4];
        attn_mma_core(sfq, sfk, sbv, tid, s, t, rows);
        if ((tid & 3) == 0) {
            #pragma unroll
            for (int i = 0; i < 4; i++) g_Umh[base + rows[i]] = t[i] / s[i];
        }
    } else {
        const int q = y;
        const uint4* fqg = reinterpret_cast<const uint4*>(g_fq);
        const uint4* fkg = reinterpret_cast<const uint4*>(g_fk);
        for (int i = tid; i < 192 * 4; i += 192) {
            const int row = i >> 2, f4 = i & 3;
            const int gidx = ((b * KPn + row) * KQn + q) * 4 + f4;
            uint4 v = fqg[gidx];
            uint32_t* dq = sfq + row * SPADH + f4 * 4;
            dq[0] = v.x; dq[1] = v.y; dq[2] = v.z; dq[3] = v.w;
            uint4 w = fkg[gidx];
            uint32_t* dk = sfk + row * SPADH + f4 * 4;
            dk[0] = w.x; dk[1] = w.y; dk[2] = w.z; dk[3] = w.w;
        }
        {
            const int idx = (b * KPn + tid) * KQn + q;
            sbv[tid] = make_float2((mask[idx] < 0.5f) ? NEGV : 0.f, g_vw[idx]);
        }
        __syncthreads();

        float s[4], t[4]; int rows[4];
        attn_mma_core(sfq, sfk, sbv, tid, s, t, rows);
        if ((tid & 3) == 0) {
            #pragma unroll
            for (int i = 0; i < 4; i++)
                g_Umv[(b * KPn + rows[i]) * KQn + q] = t[i] / s[i];
        }
    }
}

// ---------------- K4: U via tf32 MMA, 64x32 tiles (72 blocks) ----------------
__global__ __launch_bounds__(256) void k4_U(
    const float* __restrict__ Eq, const float* __restrict__ Ep,
    const float* __restrict__ W_out, const float* __restrict__ mask)
{
    __shared__ uint32_t sA[64 * 36];
    __shared__ uint32_t sB[32 * 36];
    __shared__ float sw3[Hn];

    const int b = blockIdx.z;
    const int row0 = blockIdx.y * 64;   // p
    const int col0 = blockIdx.x * 32;   // q
    const int tid = threadIdx.x;
    const int wid = tid >> 5, lane = tid & 31, g = lane >> 2, t4 = lane & 3;
    const int wr = wid & 1, wc = wid >> 1;
    float c[2][4] = {};

    for (int i = tid; i < Hn; i += 256) sw3[i] = W_out[2 * Hn + i];
    __syncthreads();

    for (int kc = 0; kc < Hn; kc += 32) {
        #pragma unroll
        for (int h = 0; h < 2; h++) {
            const int i = tid + h * 256;
            const int r = i >> 3, j4 = i & 7;
            float4 av = *reinterpret_cast<const float4*>(Ep + (b * KPn + row0 + r) * Hn + kc + j4 * 4);
            uint32_t* da = sA + r * 36 + j4 * 4;
            da[0] = tf32cvt(av.x); da[1] = tf32cvt(av.y); da[2] = tf32cvt(av.z); da[3] = tf32cvt(av.w);
        }
        {
            const int r = tid >> 3, j4 = tid & 7;
            float4 bv = *reinterpret_cast<const float4*>(Eq + (b * KQn + col0 + r) * Hn + kc + j4 * 4);
            uint32_t* db = sB + r * 36 + j4 * 4;
            db[0] = tf32cvt(bv.x * sw3[kc + j4 * 4 + 0]);
            db[1] = tf32cvt(bv.y * sw3[kc + j4 * 4 + 1]);
            db[2] = tf32cvt(bv.z * sw3[kc + j4 * 4 + 2]);
            db[3] = tf32cvt(bv.w * sw3[kc + j4 * 4 + 3]);
        }
        __syncthreads();
        #pragma unroll
        for (int ks = 0; ks < 4; ks++) {
            uint32_t a[2][4];
            #pragma unroll
            for (int mt = 0; mt < 2; mt++) {
                const int r = wr * 32 + mt * 16;
                a[mt][0] = sA[(r + g) * 36 + ks * 8 + t4];
                a[mt][1] = sA[(r + g + 8) * 36 + ks * 8 + t4];
                a[mt][2] = sA[(r + g) * 36 + ks * 8 + t4 + 4];
                a[mt][3] = sA[(r + g + 8) * 36 + ks * 8 + t4 + 4];
            }
            const uint32_t b0 = sB[(wc * 8 + g) * 36 + ks * 8 + t4];
            const uint32_t b1 = sB[(wc * 8 + g) * 36 + ks * 8 + t4 + 4];
            mma_tf32(c[0], a[0], b0, b1);
            mma_tf32(c[1], a[1], b0, b1);
        }
        __syncthreads();
    }

    #pragma unroll
    for (int mt = 0; mt < 2; mt++)
        #pragma unroll
        for (int half = 0; half < 2; half++) {
            const int row = row0 + wr * 32 + mt * 16 + g + half * 8;
            const int col = col0 + wc * 8 + 2 * t4;
            const int idx = (b * KPn + row) * KQn + col;
            const float u2v = g_u2[b * KPn + row];
            float U0 = c[mt][half * 2 + 0] + g_u1[b * KQn + col] + u2v + g_Umh[idx] + g_Umv[idx];
            float U1 = c[mt][half * 2 + 1] + g_u1[b * KQn + col + 1] + u2v + g_Umh[idx + 1] + g_Umv[idx + 1];
            if (mask[idx] < 0.5f) U0 = NEGV;
            if (mask[idx + 1] < 0.5f) U1 = NEGV;
            *reinterpret_cast<float2*>(g_U + idx) = make_float2(U0, U1);
        }
}

// ---------------- K5: both softmax aggregations (z = dir), merged ----------------
__global__ __launch_bounds__(256) void k5_soft(const float* __restrict__ Eq, const float* __restrict__ Ep)
{
    const int b = blockIdx.x, y = blockIdx.y, dir = blockIdx.z;
    __shared__ float sw[192];
    __shared__ float red[256];
    const int tid = threadIdx.x;

    float v;
    if (dir == 0) v = (tid < KQn) ? g_U[(b * KPn + y) * KQn + tid] : -3.4e38f;
    else          v = (tid < KPn) ? g_U[(b * KPn + tid) * KQn + y] : -3.4e38f;
    red[tid] = v; __syncthreads();
    for (int o = 128; o; o >>= 1) { if (tid < o) red[tid] = fmaxf(red[tid], red[tid + o]); __syncthreads(); }
    const float m = red[0]; __syncthreads();
    const float e = (tid < 192) ? __expf(v - m) : 0.f;
    red[tid] = e; __syncthreads();
    for (int o = 128; o; o >>= 1) { if (tid < o) red[tid] += red[tid + o]; __syncthreads(); }
    const float inv = 1.f / red[0];
    if (tid < 192) sw[tid] = e * inv;
    __syncthreads();

    const int h = tid;
    float a0 = 0.f, a1 = 0.f;
    if (dir == 0) {
        for (int k = 0; k < KQn; k += 2) {
            a0 += sw[k] * Eq[(b * KQn + k) * Hn + h];
            a1 += sw[k + 1] * Eq[(b * KQn + k + 1) * Hn + h];
        }
        const float a = a0 + a1;
        const float ep = Ep[(b * KPn + y) * Hn + h];
        float* G = g_Gl + (b * KPn + y) * Rn;
        G[h] = ep; G[Hn + h] = a; G[2 * Hn + h] = ep * a;
    } else {
        for (int k = 0; k < KPn; k += 2) {
            a0 += sw[k] * Ep[(b * KPn + k) * Hn + h];
            a1 += sw[k + 1] * Ep[(b * KPn + k + 1) * Hn + h];
        }
        const float a = a0 + a1;
        const float eq = Eq[(b * KQn + y) * Hn + h];
        float* G = g_Gr + (b * KQn + y) * Rn;
        G[h] = eq; G[Hn + h] = a; G[2 * Hn + h] = eq * a;
    }
}

// ---------------- K6: gates via tf32 MMA, 64x64 tile ----------------
__global__ __launch_bounds__(256) void k6_gate(
    const float* __restrict__ Wl, const float* __restrict__ bl,
    const float* __restrict__ Wr, const float* __restrict__ br)
{
    __shared__ uint32_t sG[64 * 36];
    __shared__ uint32_t sW[64 * 36];

    const int side = blockIdx.z;
    const float* __restrict__ G = side ? g_Gr : g_Gl;
    const float* __restrict__ W = side ? Wr : Wl;
    const float* __restrict__ bias = side ? br : bl;
    float* __restrict__ outp = side ? g_right : g_left;
    const int row0 = blockIdx.y * 64;
    const int col0 = blockIdx.x * 64;

    const int tid = threadIdx.x;
    const int wid = tid >> 5, lane = tid & 31, g = lane >> 2, t4 = lane & 3;
    const int wr = wid >> 2, wc = wid & 3;
    float c[2][2][4] = {};

    for (int kc = 0; kc < Rn; kc += 32) {
        #pragma unroll
        for (int h = 0; h < 2; h++) {
            const int i = tid + h * 256;
            const int r = i >> 3, j4 = i & 7;
            float4 gv = *reinterpret_cast<const float4*>(G + (row0 + r) * Rn + kc + j4 * 4);
            uint32_t* dg = sG + r * 36 + j4 * 4;
            dg[0] = tf32cvt(gv.x); dg[1] = tf32cvt(gv.y); dg[2] = tf32cvt(gv.z); dg[3] = tf32cvt(gv.w);
            float4 wv = *reinterpret_cast<const float4*>(W + (col0 + r) * Rn + kc + j4 * 4);
            uint32_t* dw = sW + r * 36 + j4 * 4;
            dw[0] = tf32cvt(wv.x); dw[1] = tf32cvt(wv.y); dw[2] = tf32cvt(wv.z); dw[3] = tf32cvt(wv.w);
        }
        __syncthreads();
        #pragma unroll
        for (int ks = 0; ks < 4; ks++) {
            uint32_t a[2][4];
            #pragma unroll
            for (int mt = 0; mt < 2; mt++) {
                const int r = wr * 32 + mt * 16;
                a[mt][0] = sG[(r + g) * 36 + ks * 8 + t4];
                a[mt][1] = sG[(r + g + 8) * 36 + ks * 8 + t4];
                a[mt][2] = sG[(r + g) * 36 + ks * 8 + t4 + 4];
                a[mt][3] = sG[(r + g + 8) * 36 + ks * 8 + t4 + 4];
            }
            #pragma unroll
            for (int nt = 0; nt < 2; nt++) {
                const uint32_t b0 = sW[(wc * 16 + nt * 8 + g) * 36 + ks * 8 + t4];
                const uint32_t b1 = sW[(wc * 16 + nt * 8 + g) * 36 + ks * 8 + t4 + 4];
                mma_tf32(c[0][nt], a[0], b0, b1);
                mma_tf32(c[1][nt], a[1], b0, b1);
            }
        }
        __syncthreads();
    }

    #pragma unroll
    for (int mt = 0; mt < 2; mt++)
        #pragma unroll
        for (int nt = 0; nt < 2; nt++) {
            const int row = row0 + wr * 32 + mt * 16 + g;
            const int col = col0 + wc * 16 + nt * 8 + 2 * t4;
            const float b0f = bias[col], b1f = bias[col + 1];
            {
                float2 gv = *reinterpret_cast<const float2*>(G + row * Rn + col);
                const float s0 = 1.f / (1.f + __expf(-(c[mt][nt][0] + b0f)));
                const float s1 = 1.f / (1.f + __expf(-(c[mt][nt][1] + b1f)));
                *reinterpret_cast<float2*>(outp + row * Rn + col) = make_float2(s0 * gv.x, s1 * gv.y);
            }
            {
                float2 gv = *reinterpret_cast<const float2*>(G + (row + 8) * Rn + col);
                const float s2 = 1.f / (1.f + __expf(-(c[mt][nt][2] + b0f)));
                const float s3 = 1.f / (1.f + __expf(-(c[mt][nt][3] + b1f)));
                *reinterpret_cast<float2*>(outp + (row + 8) * Rn + col) = make_float2(s2 * gv.x, s3 * gv.y);
            }
        }
}

// ---------------- K7: split-K partials via 3-term split-tf32 MMA ----------------
__global__ __launch_bounds__(256) void k7_partial()
{
    __shared__ uint32_t hA[64 * 36], lA[64 * 36], hB[64 * 36], lB[64 * 36];

    const int z = blockIdx.z;
    const int b = z >> 2, ksz = z & 3;
    const int kbase = ksz * 192;
    const float* __restrict__ A = g_left + b * KPn * Rn;
    const float* __restrict__ Bm = g_right + b * KQn * Rn;
    const int row0 = blockIdx.y * 64;
    const int col0 = blockIdx.x * 64;
    const int tid = threadIdx.x;
    const int wid = tid >> 5, lane = tid & 31, g = lane >> 2, t4 = lane & 3;
    const int wr = wid >> 2, wc = wid & 3;
    float c[2][2][4] = {};

    for (int kc = kbase; kc < kbase + 192; kc += 32) {
        #pragma unroll
        for (int h = 0; h < 2; h++) {
            const int i = tid + h * 256;
            const int r = i >> 3, j4 = i & 7;
            float4 av = *reinterpret_cast<const float4*>(A + (row0 + r) * Rn + kc + j4 * 4);
            float4 bv = *reinterpret_cast<const float4*>(Bm + (col0 + r) * Rn + kc + j4 * 4);
            #pragma unroll
            for (int e = 0; e < 4; e++) {
                const float xa = (&av.x)[e];
                const uint32_t ha = tf32cvt(xa);
                hA[r * 36 + j4 * 4 + e] = ha;
                lA[r * 36 + j4 * 4 + e] = tf32cvt(xa - __uint_as_float(ha));
                const float xb = (&bv.x)[e];
                const uint32_t hb = tf32cvt(xb);
                hB[r * 36 + j4 * 4 + e] = hb;
                lB[r * 36 + j4 * 4 + e] = tf32cvt(xb - __uint_as_float(hb));
            }
        }
        __syncthreads();
        #pragma unroll
        for (int ks = 0; ks < 4; ks++) {
            uint32_t aH[2][4], aL[2][4];
            #pragma unroll
            for (int mt = 0; mt < 2; mt++) {
                const int r = wr * 32 + mt * 16;
                aH[mt][0] = hA[(r + g) * 36 + ks * 8 + t4];
                aH[mt][1] = hA[(r + g + 8) * 36 + ks * 8 + t4];
                aH[mt][2] = hA[(r + g) * 36 + ks * 8 + t4 + 4];
                aH[mt][3] = hA[(r + g + 8) * 36 + ks * 8 + t4 + 4];
                aL[mt][0] = lA[(r + g) * 36 + ks * 8 + t4];
                aL[mt][1] = lA[(r + g + 8) * 36 + ks * 8 + t4];
                aL[mt][2] = lA[(r + g) * 36 + ks * 8 + t4 + 4];
                aL[mt][3] = lA[(r + g + 8) * 36 + ks * 8 + t4 + 4];
            }
            #pragma unroll
            for (int nt = 0; nt < 2; nt++) {
                const int rb = wc * 16 + nt * 8 + g;
                const uint32_t bh0 = hB[rb * 36 + ks * 8 + t4];
                const uint32_t bh1 = hB[rb * 36 + ks * 8 + t4 + 4];
                const uint32_t bl0 = lB[rb * 36 + ks * 8 + t4];
                const uint32_t bl1 = lB[rb * 36 + ks * 8 + t4 + 4];
                #pragma unroll
                for (int mt = 0; mt < 2; mt++) {
                    mma_tf32(c[mt][nt], aH[mt], bh0, bh1);
                    mma_tf32(c[mt][nt], aH[mt], bl0, bl1);
                    mma_tf32(c[mt][nt], aL[mt], bh0, bh1);
                }
            }
        }
        __syncthreads();
    }

    float* dst = g_part + ksz * (BB * KPn * KQn) + b * (KPn * KQn);
    #pragma unroll
    for (int mt = 0; mt < 2; mt++)
        #pragma unroll
        for (int nt = 0; nt < 2; nt++)
            #pragma unroll
            for (int half = 0; half < 2; half++) {
                const int row = row0 + wr * 32 + mt * 16 + g + half * 8;
                const int col = col0 + wc * 16 + nt * 8 + 2 * t4;
                *reinterpret_cast<float2*>(dst + row * KQn + col) =
                    make_float2(c[mt][nt][half * 2 + 0], c[mt][nt][half * 2 + 1]);
            }
}

// ---------------- K8: reduce split-K + relu ----------------
__global__ __launch_bounds__(256) void k8_reduce(float* __restrict__ outp)
{
    const int idx = blockIdx.x * 256 + threadIdx.x;
    const int n = BB * KPn * KQn;
    if (idx < n) {
        float s = (g_part[idx] + g_part[n + idx]) + (g_part[2 * n + idx] + g_part[3 * n + idx]);
        outp[idx] = fmaxf(s, 0.f);
    }
}

// ---------------- launch ----------------
extern "C" void kernel_launch(void* const* d_in, const int* in_sizes, int n_in,
                              void* d_out, int out_size)
{
    const float* Eq    = (const float*)d_in[0];
    const float* Ep    = (const float*)d_in[1];
    const float* mask  = (const float*)d_in[2];
    const float* W_in  = (const float*)d_in[3];
    const float* Wq    = (const float*)d_in[4];
    const float* bq    = (const float*)d_in[5];
    const float* Wk    = (const float*)d_in[6];
    const float* bk    = (const float*)d_in[7];
    const float* Wv    = (const float*)d_in[8];
    const float* bv    = (const float*)d_in[9];
    const float* Wo1   = (const float*)d_in[10];
    const float* bo1   = (const float*)d_in[11];
    const float* Wo2   = (const float*)d_in[12];
    const float* bo2   = (const float*)d_in[13];
    const float* W_out = (const float*)d_in[14];
    const float* Wl    = (const float*)d_in[15];
    const float* bl    = (const float*)d_in[16];
    const float* Wr    = (const float*)d_in[17];
    const float* br    = (const float*)d_in[18];
    float* outp = (float*)d_out;

    const int smemAttn = 2 * 192 * SPADH * 4 + 192 * 8;                // 29184 B
    cudaFuncSetAttribute(k23_attn, cudaFuncAttributeMaxDynamicSharedMemorySize, smemAttn);

    k0_rowproj<<<dim3(BB, 2, 4), dim3(32, 8)>>>(Eq, Ep, W_in, W_out);
    k0b_wv4<<<1, 32>>>(Wv, bv, W_out);
    k1_pair<<<dim3(BB, KPn), 192>>>(Eq, Ep, W_in, Wq, bq, Wk, bk, Wo1, bo1, Wo2, bo2);
    k23_attn<<<dim3(BB, 192, 2), 192, smemAttn>>>(mask);
    k4_U<<<dim3(6, 3, BB), 256>>>(Eq, Ep, W_out, mask);
    k5_soft<<<dim3(BB, 192, 2), 256>>>(Eq, Ep);
    k6_gate<<<dim3(12, 12, 2), 256>>>(Wl, bl, Wr, br);
    k7_partial<<<dim3(3, 3, 16), 256>>>();
    k8_reduce<<<dim3(576), 256>>>(outp);
}

// round 17
// speedup vs baseline: 1.2297x; 1.0316x over previous
#include <cuda_runtime.h>
#include <cuda_bf16.h>
#include <math.h>
#include <stdint.h>

#define BB 4
#define KQn 192
#define KPn 192
#define Hn 256
#define Tn 32
#define Rn 768
#define NEGV (-1e9f)
#define SCALEV (0.17677669529663687f)   // 1/sqrt(32)
#define SPADH 18                         // bf16 smem row stride in u32 words

// ---------------- scratch ----------------
static __device__ float g_A1[BB * KQn * Tn];
static __device__ float g_A2[BB * KPn * Tn];
static __device__ float g_u1[BB * KQn];
static __device__ float g_u2[BB * KPn];
static __device__ uint32_t g_fq[BB * KPn * KQn * 16];  // bf16x2 packed
static __device__ uint32_t g_fk[BB * KPn * KQn * 16];  // bf16x2 packed, pre-scaled by obv*SCALE
static __device__ float g_vw[BB * KPn * KQn];
static __device__ float g_wv4[Tn];
static __device__ float g_c0[1];
static __device__ float g_Umh[BB * KPn * KQn];
static __device__ float g_Umv[BB * KPn * KQn];
static __device__ float g_U[BB * KPn * KQn];
static __device__ float g_Gl[BB * KPn * Rn];
static __device__ float g_Gr[BB * KQn * Rn];
static __device__ float g_left[BB * KPn * Rn];
static __device__ float g_right[BB * KQn * Rn];
static __device__ float g_part[4 * BB * KPn * KQn];

__device__ __forceinline__ uint32_t tf32cvt(float x) {
    uint32_t u;
    asm("cvt.rna.tf32.f32 %0, %1;" : "=r"(u) : "f"(x));
    return u;
}

__device__ __forceinline__ uint32_t packbf(float lo, float hi) {
    __nv_bfloat162 h = __floats2bfloat162_rn(lo, hi);
    return *reinterpret_cast<uint32_t*>(&h);
}

__device__ __forceinline__ void mma_tf32(float c[4], const uint32_t a[4], uint32_t b0, uint32_t b1) {
    asm volatile("mma.sync.aligned.m16n8k8.row.col.f32.tf32.tf32.f32 "
        "{%0,%1,%2,%3}, {%4,%5,%6,%7}, {%8,%9}, {%0,%1,%2,%3};"
        : "+f"(c[0]), "+f"(c[1]), "+f"(c[2]), "+f"(c[3])
        : "r"(a[0]), "r"(a[1]), "r"(a[2]), "r"(a[3]), "r"(b0), "r"(b1));
}

__device__ __forceinline__ void mma_bf16(float c[4], const uint32_t a[4], uint32_t b0, uint32_t b1) {
    asm volatile("mma.sync.aligned.m16n8k16.row.col.f32.bf16.bf16.f32 "
        "{%0,%1,%2,%3}, {%4,%5,%6,%7}, {%8,%9}, {%0,%1,%2,%3};"
        : "+f"(c[0]), "+f"(c[1]), "+f"(c[2]), "+f"(c[3])
        : "r"(a[0]), "r"(a[1]), "r"(a[2]), "r"(a[3]), "r"(b0), "r"(b1));
}

// ---------------- K0: per-row projections A1/A2 and u1/u2 ----------------
__global__ __launch_bounds__(256) void k0_rowproj(
    const float* __restrict__ Eq, const float* __restrict__ Ep,
    const float* __restrict__ W_in, const float* __restrict__ W_out)
{
    const int b = blockIdx.x;
    const int side = blockIdx.y;
    const float* src = side ? (Ep + b * KPn * Hn) : (Eq + b * KQn * Hn);
    const int woff = side ? Hn : 0;
    float* A = side ? (g_A2 + b * KPn * Tn) : (g_A1 + b * KQn * Tn);
    float* u = side ? (g_u2 + b * KPn) : (g_u1 + b * KQn);

    __shared__ float sW[Tn][Hn + 1];
    __shared__ float swv[Hn];
    const int tid = threadIdx.y * 32 + threadIdx.x;
    for (int i = tid; i < Tn * Hn; i += 256) {
        int t = i >> 8, h = i & 255;
        sW[t][h] = W_in[t * Rn + woff + h];
    }
    for (int i = tid; i < Hn; i += 256) swv[i] = W_out[woff + i];
    __syncthreads();

    const int t = threadIdx.x;
    const int y0 = blockIdx.z * 48;
    for (int y = y0 + threadIdx.y; y < y0 + 48; y += 8) {
        const float* row = src + y * Hn;
        float p0 = 0.f, p1 = 0.f, p2 = 0.f, p3 = 0.f, up = 0.f;
        for (int h = 0; h < Hn; h += 4) {
            p0 += row[h] * sW[t][h];
            p1 += row[h + 1] * sW[t][h + 1];
            p2 += row[h + 2] * sW[t][h + 2];
            p3 += row[h + 3] * sW[t][h + 3];
        }
        for (int h = t; h < Hn; h += 32) up += row[h] * swv[h];
        #pragma unroll
        for (int o = 16; o; o >>= 1) up += __shfl_down_sync(0xffffffffu, up, o);
        A[y * Tn + t] = (p0 + p1) + (p2 + p3);
        if (t == 0) u[y] = up;
    }
}

// ---------------- K0b: wv4 = Wv^T @ w4, c0 = bv . w4 ----------------
__global__ void k0b_wv4(const float* __restrict__ Wv, const float* __restrict__ bv,
                        const float* __restrict__ W_out)
{
    const int t = threadIdx.x;
    float s = 0.f;
    for (int u = 0; u < Tn; u++) s += Wv[u * Tn + t] * W_out[Rn + u];
    g_wv4[t] = s;
    float c = bv[t] * W_out[Rn + t];
    #pragma unroll
    for (int o = 16; o; o >>= 1) c += __shfl_down_sync(0xffffffffu, c, o);
    if (t == 0) g_c0[0] = c;
}

// ---------------- K1: bf16 bilinear MMA -> E1 -> bf16 projection MMA ----------------
__global__ __launch_bounds__(192) void k1_pair(
    const float* __restrict__ Eq, const float* __restrict__ Ep,
    const float* __restrict__ W_in,
    const float* __restrict__ Wq, const float* __restrict__ bq,
    const float* __restrict__ Wk, const float* __restrict__ bk,
    const float* __restrict__ Wo1, const float* __restrict__ bo1,
    const float* __restrict__ Wo2, const float* __restrict__ bo2)
{
    __shared__ uint32_t sWbuf[32 * 130];   // W3 bf16 (stride 130); reused as Wcat (stride 18)
    __shared__ uint32_t sA[192 * SPADH];   // A chunks bf16, then E1 bf16
    __shared__ float sEpRow[Hn];
    __shared__ float sA2[Tn];

    const int b = blockIdx.x, p = blockIdx.y;
    const int tid = threadIdx.x;
    const int wid = tid >> 5, lane = tid & 31, g = lane >> 2, t4 = lane & 3;
    const int m0 = wid * 32;

    for (int i = tid; i < 32 * 64; i += 192) {
        const int t = i >> 6, h4 = i & 63;
        float4 w = reinterpret_cast<const float4*>(W_in + t * Rn + 2 * Hn)[h4];
        sWbuf[t * 130 + h4 * 2]     = packbf(w.x, w.y);
        sWbuf[t * 130 + h4 * 2 + 1] = packbf(w.z, w.w);
    }
    for (int i = tid; i < Hn / 4; i += 192)
        reinterpret_cast<float4*>(sEpRow)[i] =
            reinterpret_cast<const float4*>(Ep + (b * KPn + p) * Hn)[i];
    if (tid < Tn) sA2[tid] = g_A2[(b * KPn + p) * Tn + tid];
    __syncthreads();

    // ---- stage 1: bilinear E1 = (Eq o Ep) @ W3^T, bf16 ----
    float c1[2][4][4] = {};
    const float4* eqrow = reinterpret_cast<const float4*>(Eq + (b * KQn + tid) * Hn);
    const float4* sEpRow4 = reinterpret_cast<const float4*>(sEpRow);

    for (int kc = 0; kc < 8; kc++) {
        #pragma unroll
        for (int j = 0; j < 8; j++) {
            float4 e = eqrow[kc * 8 + j];
            float4 pp = sEpRow4[kc * 8 + j];
            sA[tid * SPADH + j * 2]     = packbf(e.x * pp.x, e.y * pp.y);
            sA[tid * SPADH + j * 2 + 1] = packbf(e.z * pp.z, e.w * pp.w);
        }
        __syncwarp();
        #pragma unroll
        for (int ks = 0; ks < 2; ks++) {
            uint32_t a[2][4];
            #pragma unroll
            for (int mt = 0; mt < 2; mt++) {
                const int r = m0 + mt * 16;
                a[mt][0] = sA[(r + g) * SPADH + ks * 8 + t4];
                a[mt][1] = sA[(r + g + 8) * SPADH + ks * 8 + t4];
                a[mt][2] = sA[(r + g) * SPADH + ks * 8 + t4 + 4];
                a[mt][3] = sA[(r + g + 8) * SPADH + ks * 8 + t4 + 4];
            }
            #pragma unroll
            for (int nt = 0; nt < 4; nt++) {
                const uint32_t b0 = sWbuf[(nt * 8 + g) * 130 + kc * 16 + ks * 8 + t4];
                const uint32_t b1 = sWbuf[(nt * 8 + g) * 130 + kc * 16 + ks * 8 + t4 + 4];
                mma_bf16(c1[0][nt], a[0], b0, b1);
                mma_bf16(c1[1][nt], a[1], b0, b1);
            }
        }
        __syncwarp();
    }

    // finalize E1 (add A1 + A2) in fragment owners; pack bf16 into sA
    #pragma unroll
    for (int mt = 0; mt < 2; mt++)
        #pragma unroll
        for (int nt = 0; nt < 4; nt++) {
            const int r0 = m0 + mt * 16 + g;
            const int col = nt * 8 + 2 * t4;
            const int w = nt * 4 + t4;
            float2 a1a = *reinterpret_cast<const float2*>(g_A1 + (b * KQn + r0) * Tn + col);
            float2 a1b = *reinterpret_cast<const float2*>(g_A1 + (b * KQn + r0 + 8) * Tn + col);
            const float s2a = sA2[col], s2b = sA2[col + 1];
            sA[r0 * SPADH + w] = packbf(c1[mt][nt][0] + a1a.x + s2a,
                                        c1[mt][nt][1] + a1a.y + s2b);
            sA[(r0 + 8) * SPADH + w] = packbf(c1[mt][nt][2] + a1b.x + s2a,
                                              c1[mt][nt][3] + a1b.y + s2b);
        }
    __syncthreads();

    // Wcat bf16 (stride 18): rows 0-31 Wo1, 32-63 Wq, 64-95 Wk, 96 wv4, 97-103 zero
    for (int i = tid; i < 104 * 16; i += 192) {
        const int n = i >> 4, wslot = i & 15;
        const int t0 = wslot * 2;
        float w0v = 0.f, w1v = 0.f;
        if (n < 32)       { w0v = Wo1[n * 32 + t0]; w1v = Wo1[n * 32 + t0 + 1]; }
        else if (n < 64)  { w0v = Wq[(n - 32) * 32 + t0]; w1v = Wq[(n - 32) * 32 + t0 + 1]; }
        else if (n < 96)  { w0v = Wk[(n - 64) * 32 + t0]; w1v = Wk[(n - 64) * 32 + t0 + 1]; }
        else if (n == 96) { w0v = g_wv4[t0]; w1v = g_wv4[t0 + 1]; }
        sWbuf[n * SPADH + wslot] = packbf(w0v, w1v);
    }
    __syncthreads();

    const int pairbase = (b * KPn + p) * KQn;
    const float bo2v = bo2[0];
    const float c0v = g_c0[0];
    float scReg[4];

    uint32_t aF[2][2][4];
    #pragma unroll
    for (int ks = 0; ks < 2; ks++)
        #pragma unroll
        for (int mt = 0; mt < 2; mt++) {
            const int r = m0 + mt * 16;
            aF[ks][mt][0] = sA[(r + g) * SPADH + ks * 8 + t4];
            aF[ks][mt][1] = sA[(r + g + 8) * SPADH + ks * 8 + t4];
            aF[ks][mt][2] = sA[(r + g) * SPADH + ks * 8 + t4 + 4];
            aF[ks][mt][3] = sA[(r + g + 8) * SPADH + ks * 8 + t4 + 4];
        }

    // G0: Wo1 -> sc
    {
        float c[2][4][4] = {};
        #pragma unroll
        for (int ks = 0; ks < 2; ks++)
            #pragma unroll
            for (int nt = 0; nt < 4; nt++) {
                const uint32_t b0 = sWbuf[(nt * 8 + g) * SPADH + ks * 8 + t4];
                const uint32_t b1 = sWbuf[(nt * 8 + g) * SPADH + ks * 8 + t4 + 4];
                mma_bf16(c[0][nt], aF[ks][0], b0, b1);
                mma_bf16(c[1][nt], aF[ks][1], b0, b1);
            }
        #pragma unroll
        for (int mt = 0; mt < 2; mt++)
            #pragma unroll
            for (int half = 0; half < 2; half++) {
                float part = 0.f;
                #pragma unroll
                for (int nt = 0; nt < 4; nt++) {
                    const int col = nt * 8 + 2 * t4;
                    part += fmaxf(c[mt][nt][half * 2 + 0] + bo1[col], 0.f) * Wo2[col]
                          + fmaxf(c[mt][nt][half * 2 + 1] + bo1[col + 1], 0.f) * Wo2[col + 1];
                }
                part += __shfl_xor_sync(0xffffffffu, part, 1);
                part += __shfl_xor_sync(0xffffffffu, part, 2);
                scReg[mt * 2 + half] = SCALEV / (1.f + __expf(-(part + bo2v)));
            }
    }

    // G1: Wq -> g_fq (bf16 packed)
    {
        float c[2][4][4] = {};
        #pragma unroll
        for (int ks = 0; ks < 2; ks++)
            #pragma unroll
            for (int nt = 0; nt < 4; nt++) {
                const uint32_t b0 = sWbuf[(32 + nt * 8 + g) * SPADH + ks * 8 + t4];
                const uint32_t b1 = sWbuf[(32 + nt * 8 + g) * SPADH + ks * 8 + t4 + 4];
                mma_bf16(c[0][nt], aF[ks][0], b0, b1);
                mma_bf16(c[1][nt], aF[ks][1], b0, b1);
            }
        #pragma unroll
        for (int mt = 0; mt < 2; mt++)
            #pragma unroll
            for (int nt = 0; nt < 4; nt++) {
                const int r0 = m0 + mt * 16 + g;
                const int w = nt * 4 + t4;
                const int col = nt * 8 + 2 * t4;
                const float b0f = bq[col], b1f = bq[col + 1];
                g_fq[(pairbase + r0) * 16 + w]     = packbf(c[mt][nt][0] + b0f, c[mt][nt][1] + b1f);
                g_fq[(pairbase + r0 + 8) * 16 + w] = packbf(c[mt][nt][2] + b0f, c[mt][nt][3] + b1f);
            }
    }

    // G2: Wk + wv4 -> g_fk (bf16 packed, scaled) + g_vw
    {
        float c[2][5][4] = {};
        #pragma unroll
        for (int ks = 0; ks < 2; ks++)
            #pragma unroll
            for (int nt = 0; nt < 5; nt++) {
                const uint32_t b0 = sWbuf[(64 + nt * 8 + g) * SPADH + ks * 8 + t4];
                const uint32_t b1 = sWbuf[(64 + nt * 8 + g) * SPADH + ks * 8 + t4 + 4];
                mma_bf16(c[0][nt], aF[ks][0], b0, b1);
                mma_bf16(c[1][nt], aF[ks][1], b0, b1);
            }
        #pragma unroll
        for (int mt = 0; mt < 2; mt++)
            #pragma unroll
            for (int nt = 0; nt < 4; nt++) {
                const int r0 = m0 + mt * 16 + g;
                const int w = nt * 4 + t4;
                const int col = nt * 8 + 2 * t4;
                const float b0f = bk[col], b1f = bk[col + 1];
                const float s0 = scReg[mt * 2 + 0], s1 = scReg[mt * 2 + 1];
                g_fk[(pairbase + r0) * 16 + w]     = packbf((c[mt][nt][0] + b0f) * s0, (c[mt][nt][1] + b1f) * s0);
                g_fk[(pairbase + r0 + 8) * 16 + w] = packbf((c[mt][nt][2] + b0f) * s1, (c[mt][nt][3] + b1f) * s1);
            }
        if (t4 == 0) {
            #pragma unroll
            for (int mt = 0; mt < 2; mt++) {
                const int r0 = m0 + mt * 16 + g;
                g_vw[pairbase + r0] = c[mt][4][0] + c0v;
                g_vw[pairbase + r0 + 8] = c[mt][4][2] + c0v;
            }
        }
    }
}

// ================= bf16 tensor-core attention core =================
__device__ __forceinline__ void attn_mma_core(
    const uint32_t* __restrict__ sfq, const uint32_t* __restrict__ sfk,
    const float2* __restrict__ sbv, int tid, float sOut[4], float tOut[4], int rows[4])
{
    const int wid = tid >> 5, lane = tid & 31;
    const int g = lane >> 2, t4 = lane & 3;
    const int m0 = wid * 32;

    uint32_t aF[2][2][4];
    #pragma unroll
    for (int ks = 0; ks < 2; ks++)
        #pragma unroll
        for (int mt = 0; mt < 2; mt++) {
            const int r = m0 + mt * 16;
            aF[ks][mt][0] = sfq[(r + g) * SPADH + ks * 8 + t4];
            aF[ks][mt][1] = sfq[(r + g + 8) * SPADH + ks * 8 + t4];
            aF[ks][mt][2] = sfq[(r + g) * SPADH + ks * 8 + t4 + 4];
            aF[ks][mt][3] = sfq[(r + g + 8) * SPADH + ks * 8 + t4 + 4];
        }

    float s[4] = {0.f, 0.f, 0.f, 0.f}, tt[4] = {0.f, 0.f, 0.f, 0.f};

    for (int nc = 0; nc < 192; nc += 32) {
        float c[2][4][4];
        #pragma unroll
        for (int mt = 0; mt < 2; mt++)
            #pragma unroll
            for (int nt = 0; nt < 4; nt++)
                #pragma unroll
                for (int r = 0; r < 4; r++) c[mt][nt][r] = 0.f;

        #pragma unroll
        for (int ks = 0; ks < 2; ks++)
            #pragma unroll
            for (int nt = 0; nt < 4; nt++) {
                const uint32_t b0 = sfk[(nc + nt * 8 + g) * SPADH + ks * 8 + t4];
                const uint32_t b1 = sfk[(nc + nt * 8 + g) * SPADH + ks * 8 + t4 + 4];
                mma_bf16(c[0][nt], aF[ks][0], b0, b1);
                mma_bf16(c[1][nt], aF[ks][1], b0, b1);
            }

        #pragma unroll
        for (int nt = 0; nt < 4; nt++) {
            const int col0 = nc + nt * 8 + 2 * t4;
            const float2 bv0 = sbv[col0];
            const float2 bv1 = sbv[col0 + 1];
            #pragma unroll
            for (int mt = 0; mt < 2; mt++) {
                const float e0 = __expf(c[mt][nt][0] + bv0.x);
                const float e1 = __expf(c[mt][nt][1] + bv1.x);
                const float e2 = __expf(c[mt][nt][2] + bv0.x);
                const float e3 = __expf(c[mt][nt][3] + bv1.x);
                s[mt * 2 + 0] += e0 + e1;
                tt[mt * 2 + 0] += e0 * bv0.y + e1 * bv1.y;
                s[mt * 2 + 1] += e2 + e3;
                tt[mt * 2 + 1] += e2 * bv0.y + e3 * bv1.y;
            }
        }
    }

    #pragma unroll
    for (int i = 0; i < 4; i++) {
        s[i] += __shfl_xor_sync(0xffffffffu, s[i], 1);
        s[i] += __shfl_xor_sync(0xffffffffu, s[i], 2);
        tt[i] += __shfl_xor_sync(0xffffffffu, tt[i], 1);
        tt[i] += __shfl_xor_sync(0xffffffffu, tt[i], 2);
        sOut[i] = s[i]; tOut[i] = tt[i];
    }
    rows[0] = m0 + g;
    rows[1] = m0 + g + 8;
    rows[2] = m0 + 16 + g;
    rows[3] = m0 + 24 + g;
}

// ---------------- K23: both attention directions (z = dir), bf16 staged ----------------
__global__ __launch_bounds__(192) void k23_attn(const float* __restrict__ mask)
{
    extern __shared__ uint32_t smem[];
    uint32_t* sfq = smem;
    uint32_t* sfk = sfq + 192 * SPADH;
    float2* sbv = reinterpret_cast<float2*>(sfk + 192 * SPADH);

    const int b = blockIdx.x, y = blockIdx.y, dir = blockIdx.z;
    const int tid = threadIdx.x;

    if (dir == 0) {
        const int base = (b * KPn + y) * KQn;
        const uint4* fq4 = reinterpret_cast<const uint4*>(g_fq + base * 16);
        const uint4* fk4 = reinterpret_cast<const uint4*>(g_fk + base * 16);
        for (int i = tid; i < 192 * 4; i += 192) {
            const int row = i >> 2, f4 = i & 3;
            uint4 v = fq4[i];
            uint32_t* dq = sfq + row * SPADH + f4 * 4;
            dq[0] = v.x; dq[1] = v.y; dq[2] = v.z; dq[3] = v.w;
            uint4 w = fk4[i];
            uint32_t* dk = sfk + row * SPADH + f4 * 4;
            dk[0] = w.x; dk[1] = w.y; dk[2] = w.z; dk[3] = w.w;
        }
        sbv[tid] = make_float2((mask[base + tid] < 0.5f) ? NEGV : 0.f, g_vw[base + tid]);
        __syncthreads();

        float s[4], t[4]; int rows[4];
        attn_mma_core(sfq, sfk, sbv, tid, s, t, rows);
        if ((tid & 3) == 0) {
            #pragma unroll
            for (int i = 0; i < 4; i++) g_Umh[base + rows[i]] = t[i] / s[i];
        }
    } else {
        const int q = y;
        const uint4* fqg = reinterpret_cast<const uint4*>(g_fq);
        const uint4* fkg = reinterpret_cast<const uint4*>(g_fk);
        for (int i = tid; i < 192 * 4; i += 192) {
            const int row = i >> 2, f4 = i & 3;
            const int gidx = ((b * KPn + row) * KQn + q) * 4 + f4;
            uint4 v = fqg[gidx];
            uint32_t* dq = sfq + row * SPADH + f4 * 4;
            dq[0] = v.x; dq[1] = v.y; dq[2] = v.z; dq[3] = v.w;
            uint4 w = fkg[gidx];
            uint32_t* dk = sfk + row * SPADH + f4 * 4;
            dk[0] = w.x; dk[1] = w.y; dk[2] = w.z; dk[3] = w.w;
        }
        {
            const int idx = (b * KPn + tid) * KQn + q;
            sbv[tid] = make_float2((mask[idx] < 0.5f) ? NEGV : 0.f, g_vw[idx]);
        }
        __syncthreads();

        float s[4], t[4]; int rows[4];
        attn_mma_core(sfq, sfk, sbv, tid, s, t, rows);
        if ((tid & 3) == 0) {
            #pragma unroll
            for (int i = 0; i < 4; i++)
                g_Umv[(b * KPn + rows[i]) * KQn + q] = t[i] / s[i];
        }
    }
}

// ---------------- K4: U via tf32 MMA, 64x32 tiles (72 blocks) ----------------
__global__ __launch_bounds__(256) void k4_U(
    const float* __restrict__ Eq, const float* __restrict__ Ep,
    const float* __restrict__ W_out, const float* __restrict__ mask)
{
    __shared__ uint32_t sA[64 * 36];
    __shared__ uint32_t sB[32 * 36];
    __shared__ float sw3[Hn];

    const int b = blockIdx.z;
    const int row0 = blockIdx.y * 64;   // p
    const int col0 = blockIdx.x * 32;   // q
    const int tid = threadIdx.x;
    const int wid = tid >> 5, lane = tid & 31, g = lane >> 2, t4 = lane & 3;
    const int wr = wid & 1, wc = wid >> 1;
    float c[2][4] = {};

    for (int i = tid; i < Hn; i += 256) sw3[i] = W_out[2 * Hn + i];
    __syncthreads();

    for (int kc = 0; kc < Hn; kc += 32) {
        #pragma unroll
        for (int h = 0; h < 2; h++) {
            const int i = tid + h * 256;
            const int r = i >> 3, j4 = i & 7;
            float4 av = *reinterpret_cast<const float4*>(Ep + (b * KPn + row0 + r) * Hn + kc + j4 * 4);
            uint32_t* da = sA + r * 36 + j4 * 4;
            da[0] = tf32cvt(av.x); da[1] = tf32cvt(av.y); da[2] = tf32cvt(av.z); da[3] = tf32cvt(av.w);
        }
        {
            const int r = tid >> 3, j4 = tid & 7;
            float4 bv = *reinterpret_cast<const float4*>(Eq + (b * KQn + col0 + r) * Hn + kc + j4 * 4);
            uint32_t* db = sB + r * 36 + j4 * 4;
            db[0] = tf32cvt(bv.x * sw3[kc + j4 * 4 + 0]);
            db[1] = tf32cvt(bv.y * sw3[kc + j4 * 4 + 1]);
            db[2] = tf32cvt(bv.z * sw3[kc + j4 * 4 + 2]);
            db[3] = tf32cvt(bv.w * sw3[kc + j4 * 4 + 3]);
        }
        __syncthreads();
        #pragma unroll
        for (int ks = 0; ks < 4; ks++) {
            uint32_t a[2][4];
            #pragma unroll
            for (int mt = 0; mt < 2; mt++) {
                const int r = wr * 32 + mt * 16;
                a[mt][0] = sA[(r + g) * 36 + ks * 8 + t4];
                a[mt][1] = sA[(r + g + 8) * 36 + ks * 8 + t4];
                a[mt][2] = sA[(r + g) * 36 + ks * 8 + t4 + 4];
                a[mt][3] = sA[(r + g + 8) * 36 + ks * 8 + t4 + 4];
            }
            const uint32_t b0 = sB[(wc * 8 + g) * 36 + ks * 8 + t4];
            const uint32_t b1 = sB[(wc * 8 + g) * 36 + ks * 8 + t4 + 4];
            mma_tf32(c[0], a[0], b0, b1);
            mma_tf32(c[1], a[1], b0, b1);
        }
        __syncthreads();
    }

    #pragma unroll
    for (int mt = 0; mt < 2; mt++)
        #pragma unroll
        for (int half = 0; half < 2; half++) {
            const int row = row0 + wr * 32 + mt * 16 + g + half * 8;
            const int col = col0 + wc * 8 + 2 * t4;
            const int idx = (b * KPn + row) * KQn + col;
            const float u2v = g_u2[b * KPn + row];
            float U0 = c[mt][half * 2 + 0] + g_u1[b * KQn + col] + u2v + g_Umh[idx] + g_Umv[idx];
            float U1 = c[mt][half * 2 + 1] + g_u1[b * KQn + col + 1] + u2v + g_Umh[idx + 1] + g_Umv[idx + 1];
            if (mask[idx] < 0.5f) U0 = NEGV;
            if (mask[idx + 1] < 0.5f) U1 = NEGV;
            *reinterpret_cast<float2*>(g_U + idx) = make_float2(U0, U1);
        }
}

// ---------------- K5: softmax aggregations, 4 rows per block (z = dir) ----------------
__global__ __launch_bounds__(256) void k5_soft(const float* __restrict__ Eq, const float* __restrict__ Ep)
{
    const int b = blockIdx.x, y0 = blockIdx.y * 4, dir = blockIdx.z;
    __shared__ float sw[4][192];
    __shared__ float red[256];
    const int tid = threadIdx.x;

    #pragma unroll
    for (int r = 0; r < 4; r++) {
        const int y = y0 + r;
        float v;
        if (dir == 0) v = (tid < KQn) ? g_U[(b * KPn + y) * KQn + tid] : -3.4e38f;
        else          v = (tid < KPn) ? g_U[(b * KPn + tid) * KQn + y] : -3.4e38f;
        red[tid] = v; __syncthreads();
        for (int o = 128; o; o >>= 1) { if (tid < o) red[tid] = fmaxf(red[tid], red[tid + o]); __syncthreads(); }
        const float m = red[0]; __syncthreads();
        const float e = (tid < 192) ? __expf(v - m) : 0.f;
        red[tid] = e; __syncthreads();
        for (int o = 128; o; o >>= 1) { if (tid < o) red[tid] += red[tid + o]; __syncthreads(); }
        const float inv = 1.f / red[0];
        if (tid < 192) sw[r][tid] = e * inv;
        __syncthreads();
    }

    const int h = tid;
    const float* __restrict__ E = dir ? Ep : Eq;      // aggregated matrix
    const float* __restrict__ Ebase = dir ? Eq : Ep;  // elementwise companion
    float acc0 = 0.f, acc1 = 0.f, acc2 = 0.f, acc3 = 0.f;
    for (int k = 0; k < 192; k++) {
        const float ev = E[(b * 192 + k) * Hn + h];
        acc0 += sw[0][k] * ev;
        acc1 += sw[1][k] * ev;
        acc2 += sw[2][k] * ev;
        acc3 += sw[3][k] * ev;
    }
    float accs[4] = {acc0, acc1, acc2, acc3};
    float* Gbase = (dir ? g_Gr : g_Gl) + b * 192 * Rn;
    #pragma unroll
    for (int r = 0; r < 4; r++) {
        const int y = y0 + r;
        const float base = Ebase[(b * 192 + y) * Hn + h];
        float* G = Gbase + y * Rn;
        G[h] = base; G[Hn + h] = accs[r]; G[2 * Hn + h] = base * accs[r];
    }
}

// ---------------- K6: gates via tf32 MMA, 64x64 tile ----------------
__global__ __launch_bounds__(256) void k6_gate(
    const float* __restrict__ Wl, const float* __restrict__ bl,
    const float* __restrict__ Wr, const float* __restrict__ br)
{
    __shared__ uint32_t sG[64 * 36];
    __shared__ uint32_t sW[64 * 36];

    const int side = blockIdx.z;
    const float* __restrict__ G = side ? g_Gr : g_Gl;
    const float* __restrict__ W = side ? Wr : Wl;
    const float* __restrict__ bias = side ? br : bl;
    float* __restrict__ outp = side ? g_right : g_left;
    const int row0 = blockIdx.y * 64;
    const int col0 = blockIdx.x * 64;

    const int tid = threadIdx.x;
    const int wid = tid >> 5, lane = tid & 31, g = lane >> 2, t4 = lane & 3;
    const int wr = wid >> 2, wc = wid & 3;
    float c[2][2][4] = {};

    for (int kc = 0; kc < Rn; kc += 32) {
        #pragma unroll
        for (int h = 0; h < 2; h++) {
            const int i = tid + h * 256;
            const int r = i >> 3, j4 = i & 7;
            float4 gv = *reinterpret_cast<const float4*>(G + (row0 + r) * Rn + kc + j4 * 4);
            uint32_t* dg = sG + r * 36 + j4 * 4;
            dg[0] = tf32cvt(gv.x); dg[1] = tf32cvt(gv.y); dg[2] = tf32cvt(gv.z); dg[3] = tf32cvt(gv.w);
            float4 wv = *reinterpret_cast<const float4*>(W + (col0 + r) * Rn + kc + j4 * 4);
            uint32_t* dw = sW + r * 36 + j4 * 4;
            dw[0] = tf32cvt(wv.x); dw[1] = tf32cvt(wv.y); dw[2] = tf32cvt(wv.z); dw[3] = tf32cvt(wv.w);
        }
        __syncthreads();
        #pragma unroll
        for (int ks = 0; ks < 4; ks++) {
            uint32_t a[2][4];
            #pragma unroll
            for (int mt = 0; mt < 2; mt++) {
                const int r = wr * 32 + mt * 16;
                a[mt][0] = sG[(r + g) * 36 + ks * 8 + t4];
                a[mt][1] = sG[(r + g + 8) * 36 + ks * 8 + t4];
                a[mt][2] = sG[(r + g) * 36 + ks * 8 + t4 + 4];
                a[mt][3] = sG[(r + g + 8) * 36 + ks * 8 + t4 + 4];
            }
            #pragma unroll
            for (int nt = 0; nt < 2; nt++) {
                const uint32_t b0 = sW[(wc * 16 + nt * 8 + g) * 36 + ks * 8 + t4];
                const uint32_t b1 = sW[(wc * 16 + nt * 8 + g) * 36 + ks * 8 + t4 + 4];
                mma_tf32(c[0][nt], a[0], b0, b1);
                mma_tf32(c[1][nt], a[1], b0, b1);
            }
        }
        __syncthreads();
    }

    #pragma unroll
    for (int mt = 0; mt < 2; mt++)
        #pragma unroll
        for (int nt = 0; nt < 2; nt++) {
            const int row = row0 + wr * 32 + mt * 16 + g;
            const int col = col0 + wc * 16 + nt * 8 + 2 * t4;
            const float b0f = bias[col], b1f = bias[col + 1];
            {
                float2 gv = *reinterpret_cast<const float2*>(G + row * Rn + col);
                const float s0 = 1.f / (1.f + __expf(-(c[mt][nt][0] + b0f)));
                const float s1 = 1.f / (1.f + __expf(-(c[mt][nt][1] + b1f)));
                *reinterpret_cast<float2*>(outp + row * Rn + col) = make_float2(s0 * gv.x, s1 * gv.y);
            }
            {
                float2 gv = *reinterpret_cast<const float2*>(G + (row + 8) * Rn + col);
                const float s2 = 1.f / (1.f + __expf(-(c[mt][nt][2] + b0f)));
                const float s3 = 1.f / (1.f + __expf(-(c[mt][nt][3] + b1f)));
                *reinterpret_cast<float2*>(outp + (row + 8) * Rn + col) = make_float2(s2 * gv.x, s3 * gv.y);
            }
        }
}

// ---------------- K7: split-K partials via 3-term split-bf16 MMA ----------------
__global__ __launch_bounds__(256) void k7_partial()
{
    __shared__ uint32_t hA[64 * SPADH], lA[64 * SPADH], hB[64 * SPADH], lB[64 * SPADH];

    const int z = blockIdx.z;
    const int b = z >> 2, ksz = z & 3;
    const int kbase = ksz * 192;
    const float* __restrict__ A = g_left + b * KPn * Rn;
    const float* __restrict__ Bm = g_right + b * KQn * Rn;
    const int row0 = blockIdx.y * 64;
    const int col0 = blockIdx.x * 64;
    const int tid = threadIdx.x;
    const int wid = tid >> 5, lane = tid & 31, g = lane >> 2, t4 = lane & 3;
    const int wr = wid >> 2, wc = wid & 3;
    float c[2][2][4] = {};

    for (int kc = kbase; kc < kbase + 192; kc += 32) {
        #pragma unroll
        for (int h = 0; h < 2; h++) {
            const int i = tid + h * 256;
            const int r = i >> 3, j4 = i & 7;
            float4 av = *reinterpret_cast<const float4*>(A + (row0 + r) * Rn + kc + j4 * 4);
            float4 bv = *reinterpret_cast<const float4*>(Bm + (col0 + r) * Rn + kc + j4 * 4);
            #pragma unroll
            for (int e2 = 0; e2 < 2; e2++) {
                const float xa0 = (&av.x)[e2 * 2], xa1 = (&av.x)[e2 * 2 + 1];
                __nv_bfloat16 ha0 = __float2bfloat16_rn(xa0), ha1 = __float2bfloat16_rn(xa1);
                __nv_bfloat162 hpa; hpa.x = ha0; hpa.y = ha1;
                hA[r * SPADH + j4 * 2 + e2] = *reinterpret_cast<uint32_t*>(&hpa);
                lA[r * SPADH + j4 * 2 + e2] = packbf(xa0 - __bfloat162float(ha0),
                                                     xa1 - __bfloat162float(ha1));
                const float xb0 = (&bv.x)[e2 * 2], xb1 = (&bv.x)[e2 * 2 + 1];
                __nv_bfloat16 hb0 = __float2bfloat16_rn(xb0), hb1 = __float2bfloat16_rn(xb1);
                __nv_bfloat162 hpb; hpb.x = hb0; hpb.y = hb1;
                hB[r * SPADH + j4 * 2 + e2] = *reinterpret_cast<uint32_t*>(&hpb);
                lB[r * SPADH + j4 * 2 + e2] = packbf(xb0 - __bfloat162float(hb0),
                                                     xb1 - __bfloat162float(hb1));
            }
        }
        __syncthreads();
        #pragma unroll
        for (int ks = 0; ks < 2; ks++) {
            uint32_t aH[2][4], aL[2][4];
            #pragma unroll
            for (int mt = 0; mt < 2; mt++) {
                const int r = wr * 32 + mt * 16;
                aH[mt][0] = hA[(r + g) * SPADH + ks * 8 + t4];
                aH[mt][1] = hA[(r + g + 8) * SPADH + ks * 8 + t4];
                aH[mt][2] = hA[(r + g) * SPADH + ks * 8 + t4 + 4];
                aH[mt][3] = hA[(r + g + 8) * SPADH + ks * 8 + t4 + 4];
                aL[mt][0] = lA[(r + g) * SPADH + ks * 8 + t4];
                aL[mt][1] = lA[(r + g + 8) * SPADH + ks * 8 + t4];
                aL[mt][2] = lA[(r + g) * SPADH + ks * 8 + t4 + 4];
                aL[mt][3] = lA[(r + g + 8) * SPADH + ks * 8 + t4 + 4];
            }
            #pragma unroll
            for (int nt = 0; nt < 2; nt++) {
                const int rb = wc * 16 + nt * 8 + g;
                const uint32_t bh0 = hB[rb * SPADH + ks * 8 + t4];
                const uint32_t bh1 = hB[rb * SPADH + ks * 8 + t4 + 4];
                const uint32_t bl0 = lB[rb * SPADH + ks * 8 + t4];
                const uint32_t bl1 = lB[rb * SPADH + ks * 8 + t4 + 4];
                #pragma unroll
                for (int mt = 0; mt < 2; mt++) {
                    mma_bf16(c[mt][nt], aH[mt], bh0, bh1);
                    mma_bf16(c[mt][nt], aH[mt], bl0, bl1);
                    mma_bf16(c[mt][nt], aL[mt], bh0, bh1);
                }
            }
        }
        __syncthreads();
    }

    float* dst = g_part + ksz * (BB * KPn * KQn) + b * (KPn * KQn);
    #pragma unroll
    for (int mt = 0; mt < 2; mt++)
        #pragma unroll
        for (int nt = 0; nt < 2; nt++)
            #pragma unroll
            for (int half = 0; half < 2; half++) {
                const int row = row0 + wr * 32 + mt * 16 + g + half * 8;
                const int col = col0 + wc * 16 + nt * 8 + 2 * t4;
                *reinterpret_cast<float2*>(dst + row * KQn + col) =
                    make_float2(c[mt][nt][half * 2 + 0], c[mt][nt][half * 2 + 1]);
            }
}

// ---------------- K8: reduce split-K + relu ----------------
__global__ __launch_bounds__(256) void k8_reduce(float* __restrict__ outp)
{
    const int idx = blockIdx.x * 256 + threadIdx.x;
    const int n = BB * KPn * KQn;
    if (idx < n) {
        float s = (g_part[idx] + g_part[n + idx]) + (g_part[2 * n + idx] + g_part[3 * n + idx]);
        outp[idx] = fmaxf(s, 0.f);
    }
}

// ---------------- launch ----------------
extern "C" void kernel_launch(void* const* d_in, const int* in_sizes, int n_in,
                              void* d_out, int out_size)
{
    const float* Eq    = (const float*)d_in[0];
    const float* Ep    = (const float*)d_in[1];
    const float* mask  = (const float*)d_in[2];
    const float* W_in  = (const float*)d_in[3];
    const float* Wq    = (const float*)d_in[4];
    const float* bq    = (const float*)d_in[5];
    const float* Wk    = (const float*)d_in[6];
    const float* bk    = (const float*)d_in[7];
    const float* Wv    = (const float*)d_in[8];
    const float* bv    = (const float*)d_in[9];
    const float* Wo1   = (const float*)d_in[10];
    const float* bo1   = (const float*)d_in[11];
    const float* Wo2   = (const float*)d_in[12];
    const float* bo2   = (const float*)d_in[13];
    const float* W_out = (const float*)d_in[14];
    const float* Wl    = (const float*)d_in[15];
    const float* bl    = (const float*)d_in[16];
    const float* Wr    = (const float*)d_in[17];
    const float* br    = (const float*)d_in[18];
    float* outp = (float*)d_out;

    const int smemAttn = 2 * 192 * SPADH * 4 + 192 * 8;                // 29184 B
    cudaFuncSetAttribute(k23_attn, cudaFuncAttributeMaxDynamicSharedMemorySize, smemAttn);

    k0_rowproj<<<dim3(BB, 2, 4), dim3(32, 8)>>>(Eq, Ep, W_in, W_out);
    k0b_wv4<<<1, 32>>>(Wv, bv, W_out);
    k1_pair<<<dim3(BB, KPn), 192>>>(Eq, Ep, W_in, Wq, bq, Wk, bk, Wo1, bo1, Wo2, bo2);
    k23_attn<<<dim3(BB, 192, 2), 192, smemAttn>>>(mask);
    k4_U<<<dim3(6, 3, BB), 256>>>(Eq, Ep, W_out, mask);
    k5_soft<<<dim3(BB, 48, 2), 256>>>(Eq, Ep);
    k6_gate<<<dim3(12, 12, 2), 256>>>(Wl, bl, Wr, br);
    k7_partial<<<dim3(3, 3, 16), 256>>>();
    k8_reduce<<<dim3(576), 256>>>(outp);
}